// round 3
// baseline (speedup 1.0000x reference)
#include <cuda_runtime.h>
#include <math.h>

#define TT 256
#define HIDN 256
#define G3 768
#define D2 512
#define D8 2048
#define S1 128
#define S2 64
#define M1 256
#define M2 128

// ---------------- static device scratch ----------------
__device__ float g_xcat [(size_t)S1*TT*HIDN];
__device__ float g_gi1  [(size_t)2*S1*TT*G3];
__device__ float g_hcat [(size_t)S1*TT*D2];
__device__ float g_h2out[(size_t)S2*TT*D2];
__device__ float g_gi2  [(size_t)2*S2*TT*G3];
__device__ float g_att  [(size_t)S2*TT*D8];
__device__ float g_h1buf[2][(size_t)M1*HIDN];
__device__ float g_h2buf[2][(size_t)M2*HIDN];
__device__ float g_csc  [(size_t)S2*TT*D2];
__device__ float g_Sc   [(size_t)S2*TT*TT];
__device__ float g_cw   [S2*TT];
__device__ float g_qw   [S2*TT];
__device__ float g_mrow [S2*TT];
__device__ float g_q2c  [S2*D2];
__device__ float g_part [32*64];

// ---------------- helpers ----------------
__device__ __forceinline__ float blk_sum(float v, float* red) {
    int t = threadIdx.x;
    red[t] = v; __syncthreads();
    for (int o = blockDim.x >> 1; o > 0; o >>= 1) {
        if (t < o) red[t] += red[t + o];
        __syncthreads();
    }
    float r = red[0]; __syncthreads();
    return r;
}
__device__ __forceinline__ float blk_max(float v, float* red) {
    int t = threadIdx.x;
    red[t] = v; __syncthreads();
    for (int o = blockDim.x >> 1; o > 0; o >>= 1) {
        if (t < o) red[t] = fmaxf(red[t], red[t + o]);
        __syncthreads();
    }
    float r = red[0]; __syncthreads();
    return r;
}
__device__ __forceinline__ float sigm(float x) { return 1.f / (1.f + __expf(-x)); }

__global__ void zero_buf(float* p, int n) {
    int i = blockIdx.x * 256 + threadIdx.x;
    if (i < n) p[i] = 0.f;
}

// embedding gather: seq 0..63 question (row s>>1), 64..127 article (row s-64)
__global__ void __launch_bounds__(256) gather_embed(
    const int* __restrict__ q, const int* __restrict__ a,
    const float* __restrict__ emb)
{
    int t = blockIdx.x, s = blockIdx.y, tid = threadIdx.x;
    int id = (s < 64) ? q[(s >> 1) * TT + t] : a[(size_t)(s - 64) * TT + t];
    g_xcat[((size_t)s * TT + t) * HIDN + tid] = emb[(size_t)id * HIDN + tid];
}

// ---------------- GEMM: C = A * W^T (+bias or +bidaf score terms) ----------------
// A:[M,K] rm, W:[N,K] rm, C:[M,N]. BM=128 BN=64 BK=16, 8x4 microtile, 256 thr.
__global__ void __launch_bounds__(256) gemm_awt(
    const float* __restrict__ Ab, const float* __restrict__ Wb, float* __restrict__ Cb,
    int M, int N, int K, long long sA, long long sW, long long sC,
    const float* __restrict__ bias, int sBias,
    const float* __restrict__ cw, const float* __restrict__ qw,
    const float* __restrict__ bvec)
{
    const int z = blockIdx.z;
    const float* A = Ab + (size_t)z * sA;
    const float* W = Wb + (size_t)z * sW;
    float* C = Cb + (size_t)z * sC;
    const int m0 = blockIdx.y * 128, n0 = blockIdx.x * 64;
    __shared__ float As[16][128];
    __shared__ float Bs[16][64];
    const int tid = threadIdx.x;
    const int tx = tid & 15, ty = tid >> 4;
    float acc[8][4];
#pragma unroll
    for (int i = 0; i < 8; i++)
#pragma unroll
        for (int j = 0; j < 4; j++) acc[i][j] = 0.f;

    for (int k0 = 0; k0 < K; k0 += 16) {
#pragma unroll
        for (int l = 0; l < 2; l++) {
            int slot = tid * 2 + l;
            int row = slot >> 2, kc = (slot & 3) << 2;
            float4 v = *(const float4*)(A + (size_t)(m0 + row) * K + k0 + kc);
            As[kc][row] = v.x; As[kc+1][row] = v.y; As[kc+2][row] = v.z; As[kc+3][row] = v.w;
        }
        {
            int nr = tid >> 2, kc = (tid & 3) << 2;
            float4 v = *(const float4*)(W + (size_t)(n0 + nr) * K + k0 + kc);
            Bs[kc][nr] = v.x; Bs[kc+1][nr] = v.y; Bs[kc+2][nr] = v.z; Bs[kc+3][nr] = v.w;
        }
        __syncthreads();
#pragma unroll
        for (int k = 0; k < 16; k++) {
            float4 a0 = *(float4*)&As[k][ty*8];
            float4 a1 = *(float4*)&As[k][ty*8+4];
            float4 b0 = *(float4*)&Bs[k][tx*4];
            float av[8] = {a0.x,a0.y,a0.z,a0.w,a1.x,a1.y,a1.z,a1.w};
            float bv[4] = {b0.x,b0.y,b0.z,b0.w};
#pragma unroll
            for (int i = 0; i < 8; i++)
#pragma unroll
                for (int j = 0; j < 4; j++) acc[i][j] += av[i] * bv[j];
        }
        __syncthreads();
    }
    float badd = bvec ? (bvec[0] + bvec[1] + bvec[2]) : 0.f;
#pragma unroll
    for (int i = 0; i < 8; i++) {
        int m = m0 + ty*8 + i;
#pragma unroll
        for (int j = 0; j < 4; j++) {
            int n = n0 + tx*4 + j;
            float v = acc[i][j];
            if (bias) v += bias[(size_t)z * sBias + n];
            if (cw)   v += cw[(size_t)z * TT + m] + qw[(size_t)z * TT + n] + badd;
            C[(size_t)m * N + n] = v;
        }
    }
}

// ---------------- c2q GEMM + full BiDAF epilogue ----------------
// per z: A[256,256] (softmaxed scores), B=q[256,512]; out 4 relu chunks, optional +=
__global__ void __launch_bounds__(256) gemm_c2q(
    const float* __restrict__ Ab, const float* __restrict__ Bb, long long sB,
    const float* __restrict__ cb, long long sCrow,
    float* __restrict__ outb, int addMode)
{
    const int z = blockIdx.z;
    const float* A = Ab + (size_t)z * TT * TT;
    const float* B = Bb + (size_t)z * sB;
    const float* c = cb + (size_t)z * sCrow;
    const float* qc = g_q2c + (size_t)z * D2;
    float* out = outb + (size_t)z * TT * D8;
    const int m0 = blockIdx.y * 128, n0 = blockIdx.x * 64;
    __shared__ float As[16][128];
    __shared__ float Bs[16][64];
    const int tid = threadIdx.x;
    const int tx = tid & 15, ty = tid >> 4;
    float acc[8][4];
#pragma unroll
    for (int i = 0; i < 8; i++)
#pragma unroll
        for (int j = 0; j < 4; j++) acc[i][j] = 0.f;

    for (int k0 = 0; k0 < TT; k0 += 16) {
#pragma unroll
        for (int l = 0; l < 2; l++) {
            int slot = tid * 2 + l;
            int row = slot >> 2, kc = (slot & 3) << 2;
            float4 v = *(const float4*)(A + (size_t)(m0 + row) * TT + k0 + kc);
            As[kc][row] = v.x; As[kc+1][row] = v.y; As[kc+2][row] = v.z; As[kc+3][row] = v.w;
        }
        {
            int kr = tid >> 4, nc = (tid & 15) << 2;
            *(float4*)&Bs[kr][nc] = *(const float4*)(B + (size_t)(k0 + kr) * D2 + n0 + nc);
        }
        __syncthreads();
#pragma unroll
        for (int k = 0; k < 16; k++) {
            float4 a0 = *(float4*)&As[k][ty*8];
            float4 a1 = *(float4*)&As[k][ty*8+4];
            float4 b0 = *(float4*)&Bs[k][tx*4];
            float av[8] = {a0.x,a0.y,a0.z,a0.w,a1.x,a1.y,a1.z,a1.w};
            float bv[4] = {b0.x,b0.y,b0.z,b0.w};
#pragma unroll
            for (int i = 0; i < 8; i++)
#pragma unroll
                for (int j = 0; j < 4; j++) acc[i][j] += av[i] * bv[j];
        }
        __syncthreads();
    }
#pragma unroll
    for (int i = 0; i < 8; i++) {
        int m = m0 + ty*8 + i;
#pragma unroll
        for (int j = 0; j < 4; j++) {
            int n = n0 + tx*4 + j;
            float cv = c[(size_t)m * D2 + n];
            float c2 = acc[i][j];
            float o0 = fmaxf(cv, 0.f);
            float o1 = fmaxf(c2, 0.f);
            float o2 = fmaxf(cv * c2, 0.f);
            float o3 = fmaxf(cv * qc[n], 0.f);
            size_t b = (size_t)m * D8 + n;
            if (addMode) {
                out[b] += o0; out[b+512] += o1; out[b+1024] += o2; out[b+1536] += o3;
            } else {
                out[b] = o0; out[b+512] = o1; out[b+1024] = o2; out[b+1536] = o3;
            }
        }
    }
}

// ---------------- fused GRU step: gh = h @ whh^T, then cell update ----------------
__global__ void __launch_bounds__(256) gru_step_p(
    const float* __restrict__ gi, const float* __restrict__ whh,
    const float* __restrict__ bhh, const float* __restrict__ hin,
    float* __restrict__ hout, float* __restrict__ seqout, int S, int t)
{
    __shared__ float hs[16][256];
    __shared__ float ws[96][65];
    const int tid = threadIdx.x;
    const int tx = tid & 31, tg = tid >> 5;
    const int j0 = blockIdx.x * 32;
    const int m0 = blockIdx.y * 16;
    const int dd = m0 / S;
    const float* wb = whh + (size_t)dd * G3 * HIDN;
    {
        int row = tid >> 4, c0 = (tid & 15) << 4;
        const float* src = hin + (size_t)(m0 + row) * HIDN + c0;
#pragma unroll
        for (int i = 0; i < 4; i++)
            *(float4*)&hs[row][c0 + i*4] = *(const float4*)(src + i*4);
    }
    float acc[2][3] = {{0,0,0},{0,0,0}};
    const int r0 = tg * 2;
    for (int kc = 0; kc < 4; kc++) {
        int k0 = kc * 64;
        __syncthreads();
#pragma unroll
        for (int i = 0; i < 6; i++) {
            int u = tid + i * 256;
            int n = u >> 4, q4 = (u & 15) << 2;
            int g = n >> 5, cc = n & 31;
            float4 v = *(const float4*)(wb + (size_t)(g * 256 + j0 + cc) * HIDN + k0 + q4);
            ws[n][q4] = v.x; ws[n][q4+1] = v.y; ws[n][q4+2] = v.z; ws[n][q4+3] = v.w;
        }
        __syncthreads();
#pragma unroll 8
        for (int k = 0; k < 64; k++) {
            int ka = k0 + k;
            float h0 = hs[r0][ka], h1 = hs[r0 + 1][ka];
            float w0 = ws[tx][k], w1 = ws[32 + tx][k], w2 = ws[64 + tx][k];
            acc[0][0] += h0 * w0; acc[0][1] += h0 * w1; acc[0][2] += h0 * w2;
            acc[1][0] += h1 * w0; acc[1][1] += h1 * w1; acc[1][2] += h1 * w2;
        }
    }
    int j = j0 + tx;
#pragma unroll
    for (int r = 0; r < 2; r++) {
        int m = m0 + r0 + r;
        int d = m / S, s = m % S;
        int tq = d ? (TT - 1 - t) : t;
        size_t gb = ((size_t)(d * S + s) * TT + tq) * G3;
        float ir = gi[gb + j], iz = gi[gb + 256 + j], inn = gi[gb + 512 + j];
        size_t bb = (size_t)d * G3;
        float ghr = acc[r][0] + bhh[bb + j];
        float ghz = acc[r][1] + bhh[bb + 256 + j];
        float ghn = acc[r][2] + bhh[bb + 512 + j];
        float rg = sigm(ir + ghr);
        float zg = sigm(iz + ghz);
        float ng = tanhf(inn + rg * ghn);
        float hold = hs[r0 + r][j];
        float hnew = (1.f - zg) * ng + zg * hold;
        hout[(size_t)m * HIDN + j] = hnew;
        seqout[((size_t)s * TT + tq) * D2 + d * HIDN + j] = hnew;
    }
}

// ---------------- BiDAF prep: cw, qw, csc ----------------
__global__ void __launch_bounds__(256) bidaf_prep(
    const float* __restrict__ cbase, const float* __restrict__ qbase,
    const float* __restrict__ w)
{
    __shared__ float red[256];
    int i = blockIdx.x, z = blockIdx.y, tid = threadIdx.x;
    const float* c = cbase + ((size_t)z * TT + i) * D2;
    const float* q = qbase + ((size_t)z * TT + i) * D2;
    float c0 = c[tid], c1 = c[tid + 256];
    float q0 = q[tid], q1 = q[tid + 256];
    float sc = c0 * w[tid] + c1 * w[tid + 256];
    float sq = q0 * w[512 + tid] + q1 * w[768 + tid];
    float* csc = g_csc + ((size_t)z * TT + i) * D2;
    csc[tid]       = c0 * w[1024 + tid];
    csc[tid + 256] = c1 * w[1280 + tid];
    float rc = blk_sum(sc, red);
    float rq = blk_sum(sq, red);
    if (tid == 0) { g_cw[z * TT + i] = rc; g_qw[z * TT + i] = rq; }
}

// softmax over last axis of S (row i of [256,256]); record row max
__global__ void __launch_bounds__(256) softmax_row()
{
    __shared__ float red[256];
    int i = blockIdx.x, z = blockIdx.y, tid = threadIdx.x;
    float* row = g_Sc + ((size_t)z * TT + i) * TT;
    float v = row[tid];
    float mx = blk_max(v, red);
    float e = __expf(v - mx);
    float sm = blk_sum(e, red);
    row[tid] = e / sm;
    if (tid == 0) g_mrow[z * TT + i] = mx;
}

// bb = softmax_i(mrow); q2c = bb @ c
__global__ void __launch_bounds__(256) q2c_kern(const float* __restrict__ cbase)
{
    __shared__ float red[256];
    __shared__ float bbuf[256];
    int z = blockIdx.x, tid = threadIdx.x;
    float v = g_mrow[z * TT + tid];
    float mx = blk_max(v, red);
    float e = __expf(v - mx);
    float sm = blk_sum(e, red);
    bbuf[tid] = e / sm;
    __syncthreads();
    const float* c = cbase + (size_t)z * TT * D2;
    float a0 = 0.f, a1 = 0.f;
    for (int i = 0; i < TT; i++) {
        float b = bbuf[i];
        a0 += b * c[(size_t)i * D2 + tid];
        a1 += b * c[(size_t)i * D2 + tid + 256];
    }
    g_q2c[(size_t)z * D2 + tid] = a0;
    g_q2c[(size_t)z * D2 + tid + 256] = a1;
}

// ---------------- final rank: max over k then dot rank_w ----------------
__global__ void __launch_bounds__(256) rank_partial(const float* __restrict__ rw)
{
    __shared__ float red[256];
    int chunk = blockIdx.x, bo = blockIdx.y, tid = threadIdx.x;
    const float* s0 = g_att + (size_t)(bo * 2) * TT * D8;
    const float* s1 = g_att + (size_t)(bo * 2 + 1) * TT * D8;
    float acc = 0.f;
    int e0 = chunk * 8192 + tid;
#pragma unroll 4
    for (int it = 0; it < 32; it++) {
        int e = e0 + it * 256;
        acc += fmaxf(s0[e], s1[e]) * rw[e];
    }
    float r = blk_sum(acc, red);
    if (tid == 0) g_part[bo * 64 + chunk] = r;
}

__global__ void rank_final(const float* __restrict__ rb, float* __restrict__ out)
{
    __shared__ float red[64];
    int bo = blockIdx.x, tid = threadIdx.x;
    red[tid] = g_part[bo * 64 + tid];
    __syncthreads();
    for (int o = 32; o > 0; o >>= 1) {
        if (tid < o) red[tid] += red[tid + o];
        __syncthreads();
    }
    if (tid == 0) out[bo] = red[0] + rb[0];
}

// ---------------- host ----------------
extern "C" void kernel_launch(void* const* d_in, const int* in_sizes, int n_in,
                              void* d_out, int out_size)
{
    const int*   question = (const int*)d_in[0];
    const int*   article  = (const int*)d_in[1];
    const float* emb      = (const float*)d_in[2];
    const float* g1_wih   = (const float*)d_in[3];
    const float* g1_whh   = (const float*)d_in[4];
    const float* g1_bih   = (const float*)d_in[5];
    const float* g1_bhh   = (const float*)d_in[6];
    const float* g2_wih   = (const float*)d_in[7];
    const float* g2_whh   = (const float*)d_in[8];
    const float* g2_bih   = (const float*)d_in[9];
    const float* g2_bhh   = (const float*)d_in[10];
    const float* b1_w     = (const float*)d_in[11];
    const float* b1_b     = (const float*)d_in[12];
    const float* b2_w     = (const float*)d_in[13];
    const float* b2_b     = (const float*)d_in[14];
    const float* rank_w   = (const float*)d_in[15];
    const float* rank_b   = (const float*)d_in[16];
    float* out = (float*)d_out;

    float *xcat, *gi1, *gi2, *hcat, *h2out, *att, *csc, *Sc, *h1b, *h2b, *cwp, *qwp;
    cudaGetSymbolAddress((void**)&xcat, g_xcat);
    cudaGetSymbolAddress((void**)&gi1,  g_gi1);
    cudaGetSymbolAddress((void**)&gi2,  g_gi2);
    cudaGetSymbolAddress((void**)&hcat, g_hcat);
    cudaGetSymbolAddress((void**)&h2out,g_h2out);
    cudaGetSymbolAddress((void**)&att,  g_att);
    cudaGetSymbolAddress((void**)&csc,  g_csc);
    cudaGetSymbolAddress((void**)&Sc,   g_Sc);
    cudaGetSymbolAddress((void**)&h1b,  g_h1buf);
    cudaGetSymbolAddress((void**)&h2b,  g_h2buf);
    cudaGetSymbolAddress((void**)&cwp,  g_cw);
    cudaGetSymbolAddress((void**)&qwp,  g_qw);

    // 1. embed
    gather_embed<<<dim3(TT, S1), 256>>>(question, article, emb);

    // 2. gi1 = xcat @ wih1^T + bih1  (per dir)
    gemm_awt<<<dim3(G3/64, (S1*TT)/128, 2), 256>>>(
        xcat, g1_wih, gi1, S1*TT, G3, HIDN,
        0LL, (long long)G3*HIDN, (long long)S1*TT*G3,
        g1_bih, G3, nullptr, nullptr, nullptr);

    // 3. layer-1 scan
    zero_buf<<<(M1*HIDN)/256, 256>>>(h1b, M1*HIDN);
    for (int t = 0; t < TT; t++)
        gru_step_p<<<dim3(8, M1/16), 256>>>(
            gi1, g1_whh, g1_bhh,
            h1b + (size_t)(t & 1) * M1 * HIDN,
            h1b + (size_t)((t+1) & 1) * M1 * HIDN,
            hcat, S1, t);

    // 4. BiDAF1: c = qh (seqs 0..63), q = ah (seqs 64..127)
    const float* cb1 = hcat;
    const float* qb1 = hcat + (size_t)64 * TT * D2;
    bidaf_prep<<<dim3(TT, S2), 256>>>(cb1, qb1, b1_w);
    gemm_awt<<<dim3(TT/64, TT/128, S2), 256>>>(
        csc, qb1, Sc, TT, TT, D2,
        (long long)TT*D2, (long long)TT*D2, (long long)TT*TT,
        nullptr, 0, cwp, qwp, b1_b);
    softmax_row<<<dim3(TT, S2), 256>>>();
    q2c_kern<<<S2, 256>>>(cb1);
    gemm_c2q<<<dim3(D2/64, TT/128, S2), 256>>>(
        Sc, qb1, (long long)TT*D2, cb1, (long long)TT*D2, att, 0);

    // 5. gi2 = att @ wih2^T + bih2
    gemm_awt<<<dim3(G3/64, (S2*TT)/128, 2), 256>>>(
        att, g2_wih, gi2, S2*TT, G3, D8,
        0LL, (long long)G3*D8, (long long)S2*TT*G3,
        g2_bih, G3, nullptr, nullptr, nullptr);

    // 6. layer-2 scan
    zero_buf<<<(M2*HIDN)/256, 256>>>(h2b, M2*HIDN);
    for (int t = 0; t < TT; t++)
        gru_step_p<<<dim3(8, M2/16), 256>>>(
            gi2, g2_whh, g2_bhh,
            h2b + (size_t)(t & 1) * M2 * HIDN,
            h2b + (size_t)((t+1) & 1) * M2 * HIDN,
            h2out, S2, t);

    // 7. BiDAF2: c = q = h2out; accumulate into att (s = att + relu(bidaf2))
    bidaf_prep<<<dim3(TT, S2), 256>>>(h2out, h2out, b2_w);
    gemm_awt<<<dim3(TT/64, TT/128, S2), 256>>>(
        csc, h2out, Sc, TT, TT, D2,
        (long long)TT*D2, (long long)TT*D2, (long long)TT*TT,
        nullptr, 0, cwp, qwp, b2_b);
    softmax_row<<<dim3(TT, S2), 256>>>();
    q2c_kern<<<S2, 256>>>(h2out);
    gemm_c2q<<<dim3(D2/64, TT/128, S2), 256>>>(
        Sc, h2out, (long long)TT*D2, h2out, (long long)TT*D2, att, 1);

    // 8. rank: max over k, dot rank_w
    rank_partial<<<dim3(64, 32), 256>>>(rank_w);
    rank_final<<<32, 64>>>(rank_b, out);
}

// round 4
// speedup vs baseline: 1.0982x; 1.0982x over previous
#include <cuda_runtime.h>
#include <math.h>
#include <stdint.h>

#define TT 256
#define HIDN 256
#define G3 768
#define D2 512
#define D8 2048
#define S1 128
#define S2 64
#define M1 256
#define M2 128

// ---------------- static device scratch ----------------
__device__ float g_xcat [(size_t)S1*TT*HIDN];
__device__ float g_gi1  [(size_t)2*S1*TT*G3];
__device__ float g_hcat [(size_t)S1*TT*D2];
__device__ float g_h2out[(size_t)S2*TT*D2];
__device__ float g_gi2  [(size_t)2*S2*TT*G3];
__device__ float g_att  [(size_t)S2*TT*D8];
__device__ float g_csc  [(size_t)S2*TT*D2];
__device__ float g_Sc   [(size_t)S2*TT*TT];
__device__ float g_cw   [S2*TT];
__device__ float g_qw   [S2*TT];
__device__ float g_mrow [S2*TT];
__device__ float g_q2c  [S2*D2];
__device__ float g_part [32*64];

// ---------------- helpers ----------------
__device__ __forceinline__ float blk_sum(float v, float* red) {
    int t = threadIdx.x;
    red[t] = v; __syncthreads();
    for (int o = blockDim.x >> 1; o > 0; o >>= 1) {
        if (t < o) red[t] += red[t + o];
        __syncthreads();
    }
    float r = red[0]; __syncthreads();
    return r;
}
__device__ __forceinline__ float blk_max(float v, float* red) {
    int t = threadIdx.x;
    red[t] = v; __syncthreads();
    for (int o = blockDim.x >> 1; o > 0; o >>= 1) {
        if (t < o) red[t] = fmaxf(red[t], red[t + o]);
        __syncthreads();
    }
    float r = red[0]; __syncthreads();
    return r;
}
__device__ __forceinline__ float sigm(float x) { return 1.f / (1.f + __expf(-x)); }

__device__ __forceinline__ void sts_remote(uint32_t laddr, int rank, float v) {
    uint32_t r;
    asm volatile("mapa.shared::cluster.u32 %0, %1, %2;" : "=r"(r) : "r"(laddr), "r"(rank));
    asm volatile("st.shared::cluster.f32 [%0], %1;" :: "r"(r), "f"(v) : "memory");
}
__device__ __forceinline__ void cluster_sync_() {
    asm volatile("barrier.cluster.arrive.aligned;" ::: "memory");
    asm volatile("barrier.cluster.wait.aligned;" ::: "memory");
}

// embedding gather
__global__ void __launch_bounds__(256) gather_embed(
    const int* __restrict__ q, const int* __restrict__ a,
    const float* __restrict__ emb)
{
    int t = blockIdx.x, s = blockIdx.y, tid = threadIdx.x;
    int id = (s < 64) ? q[(s >> 1) * TT + t] : a[(size_t)(s - 64) * TT + t];
    g_xcat[((size_t)s * TT + t) * HIDN + tid] = emb[(size_t)id * HIDN + tid];
}

// ---------------- GEMM: C = A * W^T (+bias or +bidaf score terms) ----------------
__global__ void __launch_bounds__(256) gemm_awt(
    const float* __restrict__ Ab, const float* __restrict__ Wb, float* __restrict__ Cb,
    int M, int N, int K, long long sA, long long sW, long long sC,
    const float* __restrict__ bias, int sBias,
    const float* __restrict__ cw, const float* __restrict__ qw,
    const float* __restrict__ bvec)
{
    const int z = blockIdx.z;
    const float* A = Ab + (size_t)z * sA;
    const float* W = Wb + (size_t)z * sW;
    float* C = Cb + (size_t)z * sC;
    const int m0 = blockIdx.y * 128, n0 = blockIdx.x * 64;
    __shared__ float As[16][128];
    __shared__ float Bs[16][64];
    const int tid = threadIdx.x;
    const int tx = tid & 15, ty = tid >> 4;
    float acc[8][4];
#pragma unroll
    for (int i = 0; i < 8; i++)
#pragma unroll
        for (int j = 0; j < 4; j++) acc[i][j] = 0.f;

    for (int k0 = 0; k0 < K; k0 += 16) {
#pragma unroll
        for (int l = 0; l < 2; l++) {
            int slot = tid * 2 + l;
            int row = slot >> 2, kc = (slot & 3) << 2;
            float4 v = *(const float4*)(A + (size_t)(m0 + row) * K + k0 + kc);
            As[kc][row] = v.x; As[kc+1][row] = v.y; As[kc+2][row] = v.z; As[kc+3][row] = v.w;
        }
        {
            int nr = tid >> 2, kc = (tid & 3) << 2;
            float4 v = *(const float4*)(W + (size_t)(n0 + nr) * K + k0 + kc);
            Bs[kc][nr] = v.x; Bs[kc+1][nr] = v.y; Bs[kc+2][nr] = v.z; Bs[kc+3][nr] = v.w;
        }
        __syncthreads();
#pragma unroll
        for (int k = 0; k < 16; k++) {
            float4 a0 = *(float4*)&As[k][ty*8];
            float4 a1 = *(float4*)&As[k][ty*8+4];
            float4 b0 = *(float4*)&Bs[k][tx*4];
            float av[8] = {a0.x,a0.y,a0.z,a0.w,a1.x,a1.y,a1.z,a1.w};
            float bv[4] = {b0.x,b0.y,b0.z,b0.w};
#pragma unroll
            for (int i = 0; i < 8; i++)
#pragma unroll
                for (int j = 0; j < 4; j++) acc[i][j] += av[i] * bv[j];
        }
        __syncthreads();
    }
    float badd = bvec ? (bvec[0] + bvec[1] + bvec[2]) : 0.f;
#pragma unroll
    for (int i = 0; i < 8; i++) {
        int m = m0 + ty*8 + i;
#pragma unroll
        for (int j = 0; j < 4; j++) {
            int n = n0 + tx*4 + j;
            float v = acc[i][j];
            if (bias) v += bias[(size_t)z * sBias + n];
            if (cw)   v += cw[(size_t)z * TT + m] + qw[(size_t)z * TT + n] + badd;
            C[(size_t)m * N + n] = v;
        }
    }
}

// ---------------- c2q GEMM + full BiDAF epilogue ----------------
__global__ void __launch_bounds__(256) gemm_c2q(
    const float* __restrict__ Ab, const float* __restrict__ Bb, long long sB,
    const float* __restrict__ cb, long long sCrow,
    float* __restrict__ outb, int addMode)
{
    const int z = blockIdx.z;
    const float* A = Ab + (size_t)z * TT * TT;
    const float* B = Bb + (size_t)z * sB;
    const float* c = cb + (size_t)z * sCrow;
    const float* qc = g_q2c + (size_t)z * D2;
    float* out = outb + (size_t)z * TT * D8;
    const int m0 = blockIdx.y * 128, n0 = blockIdx.x * 64;
    __shared__ float As[16][128];
    __shared__ float Bs[16][64];
    const int tid = threadIdx.x;
    const int tx = tid & 15, ty = tid >> 4;
    float acc[8][4];
#pragma unroll
    for (int i = 0; i < 8; i++)
#pragma unroll
        for (int j = 0; j < 4; j++) acc[i][j] = 0.f;

    for (int k0 = 0; k0 < TT; k0 += 16) {
#pragma unroll
        for (int l = 0; l < 2; l++) {
            int slot = tid * 2 + l;
            int row = slot >> 2, kc = (slot & 3) << 2;
            float4 v = *(const float4*)(A + (size_t)(m0 + row) * TT + k0 + kc);
            As[kc][row] = v.x; As[kc+1][row] = v.y; As[kc+2][row] = v.z; As[kc+3][row] = v.w;
        }
        {
            int kr = tid >> 4, nc = (tid & 15) << 2;
            *(float4*)&Bs[kr][nc] = *(const float4*)(B + (size_t)(k0 + kr) * D2 + n0 + nc);
        }
        __syncthreads();
#pragma unroll
        for (int k = 0; k < 16; k++) {
            float4 a0 = *(float4*)&As[k][ty*8];
            float4 a1 = *(float4*)&As[k][ty*8+4];
            float4 b0 = *(float4*)&Bs[k][tx*4];
            float av[8] = {a0.x,a0.y,a0.z,a0.w,a1.x,a1.y,a1.z,a1.w};
            float bv[4] = {b0.x,b0.y,b0.z,b0.w};
#pragma unroll
            for (int i = 0; i < 8; i++)
#pragma unroll
                for (int j = 0; j < 4; j++) acc[i][j] += av[i] * bv[j];
        }
        __syncthreads();
    }
#pragma unroll
    for (int i = 0; i < 8; i++) {
        int m = m0 + ty*8 + i;
#pragma unroll
        for (int j = 0; j < 4; j++) {
            int n = n0 + tx*4 + j;
            float cv = c[(size_t)m * D2 + n];
            float c2 = acc[i][j];
            float o0 = fmaxf(cv, 0.f);
            float o1 = fmaxf(c2, 0.f);
            float o2 = fmaxf(cv * c2, 0.f);
            float o3 = fmaxf(cv * qc[n], 0.f);
            size_t b = (size_t)m * D8 + n;
            if (addMode) {
                out[b] += o0; out[b+512] += o1; out[b+1024] += o2; out[b+1536] += o3;
            } else {
                out[b] = o0; out[b+512] = o1; out[b+1024] = o2; out[b+1536] = o3;
            }
        }
    }
}

// ---------------- persistent GRU scan (one launch per layer) ----------------
// grid (8 j-tiles, M/16 stream-tiles); cluster = the 8 j-tiles of one stream-tile.
// smem: ws[96][257] weights (loaded once) + hs[2][16][256] double-buffered h.
#define WS_STRIDE 257
#define WS_FLOATS (96 * WS_STRIDE)
#define HS_FLOATS (2 * 16 * 256)
#define SCAN_SMEM ((WS_FLOATS + HS_FLOATS) * 4)

__global__ void __cluster_dims__(8, 1, 1) __launch_bounds__(256)
gru_scan(const float* __restrict__ gi, const float* __restrict__ whh,
         const float* __restrict__ bhh, float* __restrict__ seqout, int S)
{
    extern __shared__ float sm[];
    float* ws  = sm;                 // [96][257]
    float* hsb = sm + WS_FLOATS;     // [2][16][256]

    const int tid = threadIdx.x;
    const int tx = tid & 31, tg = tid >> 5;
    const int j0 = blockIdx.x * 32;
    const int m0 = blockIdx.y * 16;
    const int dd = m0 / S;           // direction, uniform per CTA
    const int j = j0 + tx;
    const int r0 = tg * 2;

    // load weight slice once: rows = gate*32 + cc, cols = k (stride 257)
    const float* wb = whh + (size_t)dd * G3 * HIDN;
    for (int idx = tid; idx < 96 * 64; idx += 256) {
        int row = idx >> 6;
        int kq = (idx & 63) << 2;
        int g = row >> 5, cc = row & 31;
        float4 v = *(const float4*)(wb + (size_t)(g * 256 + j0 + cc) * HIDN + kq);
        float* d = ws + row * WS_STRIDE + kq;
        d[0] = v.x; d[1] = v.y; d[2] = v.z; d[3] = v.w;
    }
    // zero h buffer 0
    for (int i = tid; i < 16 * 256; i += 256) hsb[i] = 0.f;

    const float b0 = bhh[(size_t)dd * G3 + j];
    const float b1 = bhh[(size_t)dd * G3 + 256 + j];
    const float b2 = bhh[(size_t)dd * G3 + 512 + j];

    // per-thread stream info (2 streams: r0, r0+1)
    const int mA = m0 + r0, mB = m0 + r0 + 1;
    const int sA = mA - dd * S, sB = mB - dd * S;
    const size_t giA = ((size_t)(dd * S + sA)) * TT * G3;
    const size_t giB = ((size_t)(dd * S + sB)) * TT * G3;

    const float* w0p = ws + (size_t)tx * WS_STRIDE;
    const float* w1p = ws + (size_t)(32 + tx) * WS_STRIDE;
    const float* w2p = ws + (size_t)(64 + tx) * WS_STRIDE;

    cluster_sync_();  // weights + h0 ready cluster-wide

    for (int t = 0; t < TT; t++) {
        const float* hc = hsb + (t & 1) * 4096;
        float* hn = hsb + ((t + 1) & 1) * 4096;
        const float* hA = hc + r0 * 256;
        const float* hB = hc + (r0 + 1) * 256;

        float a00 = 0.f, a01 = 0.f, a02 = 0.f;
        float a10 = 0.f, a11 = 0.f, a12 = 0.f;
#pragma unroll 8
        for (int k = 0; k < 256; k++) {
            float h0 = hA[k], h1 = hB[k];
            float w0 = w0p[k], w1 = w1p[k], w2 = w2p[k];
            a00 += h0 * w0; a01 += h0 * w1; a02 += h0 * w2;
            a10 += h1 * w0; a11 += h1 * w1; a12 += h1 * w2;
        }

        const int tq = dd ? (TT - 1 - t) : t;
#pragma unroll
        for (int r = 0; r < 2; r++) {
            size_t gb = (r ? giB : giA) + (size_t)tq * G3;
            float ir  = gi[gb + j];
            float iz  = gi[gb + 256 + j];
            float inn = gi[gb + 512 + j];
            float g0 = r ? a10 : a00;
            float g1 = r ? a11 : a01;
            float g2 = r ? a12 : a02;
            float rg = sigm(ir + g0 + b0);
            float zg = sigm(iz + g1 + b1);
            float ng = tanhf(inn + rg * (g2 + b2));
            float hold = hc[(r0 + r) * 256 + j];
            float hnew = (1.f - zg) * ng + zg * hold;
            int s = r ? sB : sA;
            seqout[((size_t)s * TT + tq) * D2 + dd * HIDN + j] = hnew;
            uint32_t la = (uint32_t)__cvta_generic_to_shared(&hn[(r0 + r) * 256 + j]);
#pragma unroll
            for (int rk = 0; rk < 8; rk++) sts_remote(la, rk, hnew);
        }
        cluster_sync_();
    }
}

// ---------------- BiDAF prep: cw, qw, csc ----------------
__global__ void __launch_bounds__(256) bidaf_prep(
    const float* __restrict__ cbase, const float* __restrict__ qbase,
    const float* __restrict__ w)
{
    __shared__ float red[256];
    int i = blockIdx.x, z = blockIdx.y, tid = threadIdx.x;
    const float* c = cbase + ((size_t)z * TT + i) * D2;
    const float* q = qbase + ((size_t)z * TT + i) * D2;
    float c0 = c[tid], c1 = c[tid + 256];
    float q0 = q[tid], q1 = q[tid + 256];
    float sc = c0 * w[tid] + c1 * w[tid + 256];
    float sq = q0 * w[512 + tid] + q1 * w[768 + tid];
    float* csc = g_csc + ((size_t)z * TT + i) * D2;
    csc[tid]       = c0 * w[1024 + tid];
    csc[tid + 256] = c1 * w[1280 + tid];
    float rc = blk_sum(sc, red);
    float rq = blk_sum(sq, red);
    if (tid == 0) { g_cw[z * TT + i] = rc; g_qw[z * TT + i] = rq; }
}

__global__ void __launch_bounds__(256) softmax_row()
{
    __shared__ float red[256];
    int i = blockIdx.x, z = blockIdx.y, tid = threadIdx.x;
    float* row = g_Sc + ((size_t)z * TT + i) * TT;
    float v = row[tid];
    float mx = blk_max(v, red);
    float e = __expf(v - mx);
    float sm = blk_sum(e, red);
    row[tid] = e / sm;
    if (tid == 0) g_mrow[z * TT + i] = mx;
}

__global__ void __launch_bounds__(256) q2c_kern(const float* __restrict__ cbase)
{
    __shared__ float red[256];
    __shared__ float bbuf[256];
    int z = blockIdx.x, tid = threadIdx.x;
    float v = g_mrow[z * TT + tid];
    float mx = blk_max(v, red);
    float e = __expf(v - mx);
    float sm = blk_sum(e, red);
    bbuf[tid] = e / sm;
    __syncthreads();
    const float* c = cbase + (size_t)z * TT * D2;
    float a0 = 0.f, a1 = 0.f;
    for (int i = 0; i < TT; i++) {
        float b = bbuf[i];
        a0 += b * c[(size_t)i * D2 + tid];
        a1 += b * c[(size_t)i * D2 + tid + 256];
    }
    g_q2c[(size_t)z * D2 + tid] = a0;
    g_q2c[(size_t)z * D2 + tid + 256] = a1;
}

// ---------------- final rank ----------------
__global__ void __launch_bounds__(256) rank_partial(const float* __restrict__ rw)
{
    __shared__ float red[256];
    int chunk = blockIdx.x, bo = blockIdx.y, tid = threadIdx.x;
    const float* s0 = g_att + (size_t)(bo * 2) * TT * D8;
    const float* s1 = g_att + (size_t)(bo * 2 + 1) * TT * D8;
    float acc = 0.f;
    int e0 = chunk * 8192 + tid;
#pragma unroll 4
    for (int it = 0; it < 32; it++) {
        int e = e0 + it * 256;
        acc += fmaxf(s0[e], s1[e]) * rw[e];
    }
    float r = blk_sum(acc, red);
    if (tid == 0) g_part[bo * 64 + chunk] = r;
}

__global__ void rank_final(const float* __restrict__ rb, float* __restrict__ out)
{
    __shared__ float red[64];
    int bo = blockIdx.x, tid = threadIdx.x;
    red[tid] = g_part[bo * 64 + tid];
    __syncthreads();
    for (int o = 32; o > 0; o >>= 1) {
        if (tid < o) red[tid] += red[tid + o];
        __syncthreads();
    }
    if (tid == 0) out[bo] = red[0] + rb[0];
}

// ---------------- host ----------------
extern "C" void kernel_launch(void* const* d_in, const int* in_sizes, int n_in,
                              void* d_out, int out_size)
{
    const int*   question = (const int*)d_in[0];
    const int*   article  = (const int*)d_in[1];
    const float* emb      = (const float*)d_in[2];
    const float* g1_wih   = (const float*)d_in[3];
    const float* g1_whh   = (const float*)d_in[4];
    const float* g1_bih   = (const float*)d_in[5];
    const float* g1_bhh   = (const float*)d_in[6];
    const float* g2_wih   = (const float*)d_in[7];
    const float* g2_whh   = (const float*)d_in[8];
    const float* g2_bih   = (const float*)d_in[9];
    const float* g2_bhh   = (const float*)d_in[10];
    const float* b1_w     = (const float*)d_in[11];
    const float* b1_b     = (const float*)d_in[12];
    const float* b2_w     = (const float*)d_in[13];
    const float* b2_b     = (const float*)d_in[14];
    const float* rank_w   = (const float*)d_in[15];
    const float* rank_b   = (const float*)d_in[16];
    float* out = (float*)d_out;

    float *xcat, *gi1, *gi2, *hcat, *h2out, *att, *csc, *Sc, *cwp, *qwp;
    cudaGetSymbolAddress((void**)&xcat, g_xcat);
    cudaGetSymbolAddress((void**)&gi1,  g_gi1);
    cudaGetSymbolAddress((void**)&gi2,  g_gi2);
    cudaGetSymbolAddress((void**)&hcat, g_hcat);
    cudaGetSymbolAddress((void**)&h2out,g_h2out);
    cudaGetSymbolAddress((void**)&att,  g_att);
    cudaGetSymbolAddress((void**)&csc,  g_csc);
    cudaGetSymbolAddress((void**)&Sc,   g_Sc);
    cudaGetSymbolAddress((void**)&cwp,  g_cw);
    cudaGetSymbolAddress((void**)&qwp,  g_qw);

    cudaFuncSetAttribute(gru_scan, cudaFuncAttributeMaxDynamicSharedMemorySize, SCAN_SMEM);

    // 1. embed
    gather_embed<<<dim3(TT, S1), 256>>>(question, article, emb);

    // 2. gi1 = xcat @ wih1^T + bih1
    gemm_awt<<<dim3(G3/64, (S1*TT)/128, 2), 256>>>(
        xcat, g1_wih, gi1, S1*TT, G3, HIDN,
        0LL, (long long)G3*HIDN, (long long)S1*TT*G3,
        g1_bih, G3, nullptr, nullptr, nullptr);

    // 3. layer-1 scan (persistent, cluster-8)
    gru_scan<<<dim3(8, M1/16), 256, SCAN_SMEM>>>(gi1, g1_whh, g1_bhh, hcat, S1);

    // 4. BiDAF1
    const float* cb1 = hcat;
    const float* qb1 = hcat + (size_t)64 * TT * D2;
    bidaf_prep<<<dim3(TT, S2), 256>>>(cb1, qb1, b1_w);
    gemm_awt<<<dim3(TT/64, TT/128, S2), 256>>>(
        csc, qb1, Sc, TT, TT, D2,
        (long long)TT*D2, (long long)TT*D2, (long long)TT*TT,
        nullptr, 0, cwp, qwp, b1_b);
    softmax_row<<<dim3(TT, S2), 256>>>();
    q2c_kern<<<S2, 256>>>(cb1);
    gemm_c2q<<<dim3(D2/64, TT/128, S2), 256>>>(
        Sc, qb1, (long long)TT*D2, cb1, (long long)TT*D2, att, 0);

    // 5. gi2 = att @ wih2^T + bih2
    gemm_awt<<<dim3(G3/64, (S2*TT)/128, 2), 256>>>(
        att, g2_wih, gi2, S2*TT, G3, D8,
        0LL, (long long)G3*D8, (long long)S2*TT*G3,
        g2_bih, G3, nullptr, nullptr, nullptr);

    // 6. layer-2 scan
    gru_scan<<<dim3(8, M2/16), 256, SCAN_SMEM>>>(gi2, g2_whh, g2_bhh, h2out, S2);

    // 7. BiDAF2 (accumulate into att)
    bidaf_prep<<<dim3(TT, S2), 256>>>(h2out, h2out, b2_w);
    gemm_awt<<<dim3(TT/64, TT/128, S2), 256>>>(
        csc, h2out, Sc, TT, TT, D2,
        (long long)TT*D2, (long long)TT*D2, (long long)TT*TT,
        nullptr, 0, cwp, qwp, b2_b);
    softmax_row<<<dim3(TT, S2), 256>>>();
    q2c_kern<<<S2, 256>>>(h2out);
    gemm_c2q<<<dim3(D2/64, TT/128, S2), 256>>>(
        Sc, h2out, (long long)TT*D2, h2out, (long long)TT*D2, att, 1);

    // 8. rank
    rank_partial<<<dim3(64, 32), 256>>>(rank_w);
    rank_final<<<32, 64>>>(rank_b, out);
}

// round 6
// speedup vs baseline: 1.3610x; 1.2393x over previous
#include <cuda_runtime.h>
#include <cuda_bf16.h>
#include <math.h>
#include <stdint.h>

#define TT 256
#define HIDN 256
#define G3 768
#define D2 512
#define D8 2048
#define S1 128
#define S2 64
#define M1 256
#define M2 128

// ---------------- static device scratch ----------------
__device__ float g_xcat [(size_t)S1*TT*HIDN];
__device__ float g_gi1  [(size_t)2*S1*TT*G3];
__device__ float g_hcat [(size_t)S1*TT*D2];
__device__ float g_h2out[(size_t)S2*TT*D2];
__device__ float g_gi2  [(size_t)2*S2*TT*G3];
__device__ float g_att  [(size_t)S2*TT*D8];
__device__ float g_csc  [(size_t)S2*TT*D2];
__device__ float g_Sc   [(size_t)S2*TT*TT];
__device__ float g_cw   [S2*TT];
__device__ float g_qw   [S2*TT];
__device__ float g_mrow [S2*TT];
__device__ float g_q2c  [S2*D2];
__device__ float g_part [32*64];

// ---------------- generic helpers ----------------
__device__ __forceinline__ float blk_sum(float v, float* red) {
    int t = threadIdx.x;
    red[t] = v; __syncthreads();
    for (int o = blockDim.x >> 1; o > 0; o >>= 1) {
        if (t < o) red[t] += red[t + o];
        __syncthreads();
    }
    float r = red[0]; __syncthreads();
    return r;
}
__device__ __forceinline__ float blk_max(float v, float* red) {
    int t = threadIdx.x;
    red[t] = v; __syncthreads();
    for (int o = blockDim.x >> 1; o > 0; o >>= 1) {
        if (t < o) red[t] = fmaxf(red[t], red[t + o]);
        __syncthreads();
    }
    float r = red[0]; __syncthreads();
    return r;
}
__device__ __forceinline__ float sigm(float x) { return 1.f / (1.f + __expf(-x)); }

__device__ __forceinline__ void sts_remote(uint32_t laddr, int rank, float v) {
    uint32_t r;
    asm volatile("mapa.shared::cluster.u32 %0, %1, %2;" : "=r"(r) : "r"(laddr), "r"(rank));
    asm volatile("st.shared::cluster.f32 [%0], %1;" :: "r"(r), "f"(v) : "memory");
}
__device__ __forceinline__ void cluster_sync_() {
    asm volatile("barrier.cluster.arrive.aligned;" ::: "memory");
    asm volatile("barrier.cluster.wait.aligned;" ::: "memory");
}

// ---------------- embedding gather ----------------
__global__ void __launch_bounds__(256) gather_embed(
    const int* __restrict__ q, const int* __restrict__ a,
    const float* __restrict__ emb)
{
    int t = blockIdx.x, s = blockIdx.y, tid = threadIdx.x;
    int id = (s < 64) ? q[(s >> 1) * TT + t] : a[(size_t)(s - 64) * TT + t];
    g_xcat[((size_t)s * TT + t) * HIDN + tid] = emb[(size_t)id * HIDN + tid];
}

// ---------------- split-bf16 helpers ----------------
__device__ __forceinline__ uint32_t pk2(__nv_bfloat16 a, __nv_bfloat16 b) {
    return (uint32_t)__bfloat16_as_ushort(a) | ((uint32_t)__bfloat16_as_ushort(b) << 16);
}
__device__ __forceinline__ void split8(const float* f, uint4& hi, uint4& lo) {
    __nv_bfloat16 h[8]; float l[8];
#pragma unroll
    for (int i = 0; i < 8; i++) {
        h[i] = __float2bfloat16(f[i]);
        l[i] = f[i] - __bfloat162float(h[i]);
    }
    hi = make_uint4(pk2(h[0],h[1]), pk2(h[2],h[3]), pk2(h[4],h[5]), pk2(h[6],h[7]));
    lo = make_uint4(pk2(__float2bfloat16(l[0]),__float2bfloat16(l[1])),
                    pk2(__float2bfloat16(l[2]),__float2bfloat16(l[3])),
                    pk2(__float2bfloat16(l[4]),__float2bfloat16(l[5])),
                    pk2(__float2bfloat16(l[6]),__float2bfloat16(l[7])));
}

#define LDMX4(r0,r1,r2,r3,addr) \
    asm volatile("ldmatrix.sync.aligned.m8n8.x4.shared.b16 {%0,%1,%2,%3}, [%4];" \
        : "=r"(r0), "=r"(r1), "=r"(r2), "=r"(r3) : "r"(addr))

#define MMA16816(c0,c1,c2,c3,a0,a1,a2,a3,b0,b1) \
    asm volatile("mma.sync.aligned.m16n8k16.row.col.f32.bf16.bf16.f32 " \
        "{%0,%1,%2,%3}, {%4,%5,%6,%7}, {%8,%9}, {%0,%1,%2,%3};" \
        : "+f"(c0), "+f"(c1), "+f"(c2), "+f"(c3) \
        : "r"(a0), "r"(a1), "r"(a2), "r"(a3), "r"(b0), "r"(b1))

// ---------------- mma.sync split-bf16 GEMM: C = A * W^T + bias ----------------
// A:[M,K] fp32 (shared across dirs); W:[2][768][K]; C:[2][M][768]
// BM=128 BN=64 BK=32; 8 warps 4m x 2n; warp tile 32x32.
#define SKP 40

__global__ void __launch_bounds__(256) gemm_mma(
    const float* __restrict__ Ab, const float* __restrict__ Wb,
    float* __restrict__ Cb, const float* __restrict__ biasb,
    int M, int K)
{
    __shared__ __nv_bfloat16 As[2][128][SKP];
    __shared__ __nv_bfloat16 Bs[2][64][SKP];
    const int tid = threadIdx.x;
    const int wid = tid >> 5, lane = tid & 31;
    const int z = blockIdx.z;
    const int m0 = blockIdx.y * 128, n0 = blockIdx.x * 64;
    const float* A = Ab;
    const float* W = Wb + (size_t)z * G3 * K;
    float* C = Cb + (size_t)z * (size_t)M * G3;
    const float* bias = biasb + (size_t)z * G3;

    const int wm = (wid & 3) * 32;
    const int wn = (wid >> 2) * 32;

    float acc[2][4][4];
#pragma unroll
    for (int i = 0; i < 2; i++)
#pragma unroll
        for (int j = 0; j < 4; j++)
#pragma unroll
            for (int q = 0; q < 4; q++) acc[i][j][q] = 0.f;

    const int lrow = ((lane >> 3) & 1) * 8 + (lane & 7);
    const int lk8 = (lane >> 4) * 8;

    for (int k0 = 0; k0 < K; k0 += 32) {
#pragma unroll
        for (int it = 0; it < 2; it++) {
            int gidx = tid + it * 256;
            int r = gidx >> 2, cg = gidx & 3;
            const float* src = A + (size_t)(m0 + r) * K + k0 + cg * 8;
            float f[8];
            *(float4*)&f[0] = *(const float4*)src;
            *(float4*)&f[4] = *(const float4*)(src + 4);
            uint4 hi, lo; split8(f, hi, lo);
            *(uint4*)&As[0][r][cg * 8] = hi;
            *(uint4*)&As[1][r][cg * 8] = lo;
        }
        {
            int r = tid >> 2, cg = tid & 3;
            const float* src = W + (size_t)(n0 + r) * K + k0 + cg * 8;
            float f[8];
            *(float4*)&f[0] = *(const float4*)src;
            *(float4*)&f[4] = *(const float4*)(src + 4);
            uint4 hi, lo; split8(f, hi, lo);
            *(uint4*)&Bs[0][r][cg * 8] = hi;
            *(uint4*)&Bs[1][r][cg * 8] = lo;
        }
        __syncthreads();
#pragma unroll
        for (int kk = 0; kk < 32; kk += 16) {
            uint32_t aF[2][2][4], bF[2][2][4];
#pragma unroll
            for (int s = 0; s < 2; s++) {
#pragma unroll
                for (int mi = 0; mi < 2; mi++) {
                    uint32_t ad = (uint32_t)__cvta_generic_to_shared(
                        &As[s][wm + mi * 16 + lrow][kk + lk8]);
                    LDMX4(aF[s][mi][0], aF[s][mi][1], aF[s][mi][2], aF[s][mi][3], ad);
                }
#pragma unroll
                for (int nj2 = 0; nj2 < 2; nj2++) {
                    uint32_t ad = (uint32_t)__cvta_generic_to_shared(
                        &Bs[s][wn + nj2 * 16 + lrow][kk + lk8]);
                    LDMX4(bF[s][nj2][0], bF[s][nj2][1], bF[s][nj2][2], bF[s][nj2][3], ad);
                }
            }
#pragma unroll
            for (int term = 0; term < 3; term++) {
                const int sa = (term == 2) ? 1 : 0;
                const int sb = (term == 1) ? 1 : 0;
#pragma unroll
                for (int mi = 0; mi < 2; mi++)
#pragma unroll
                    for (int nj = 0; nj < 4; nj++) {
                        int nj2 = nj >> 1, odd = nj & 1;
                        MMA16816(acc[mi][nj][0], acc[mi][nj][1], acc[mi][nj][2], acc[mi][nj][3],
                                 aF[sa][mi][0], aF[sa][mi][1], aF[sa][mi][2], aF[sa][mi][3],
                                 bF[sb][nj2][odd], bF[sb][nj2][2 + odd]);
                    }
            }
        }
        __syncthreads();
    }
    // epilogue: add bias, store
    const int g = lane >> 2, t4 = lane & 3;
#pragma unroll
    for (int mi = 0; mi < 2; mi++) {
        int mrow = m0 + wm + mi * 16 + g;
#pragma unroll
        for (int nj = 0; nj < 4; nj++) {
            int ncol = n0 + wn + nj * 8 + t4 * 2;
            float b0v = bias[ncol], b1v = bias[ncol + 1];
            float2 v0 = make_float2(acc[mi][nj][0] + b0v, acc[mi][nj][1] + b1v);
            float2 v1 = make_float2(acc[mi][nj][2] + b0v, acc[mi][nj][3] + b1v);
            *(float2*)&C[(size_t)mrow * G3 + ncol] = v0;
            *(float2*)&C[(size_t)(mrow + 8) * G3 + ncol] = v1;
        }
    }
}

// ---------------- SIMT GEMM (BiDAF scores): C = A * W^T + epilogue ----------------
__global__ void __launch_bounds__(256) gemm_awt(
    const float* __restrict__ Ab, const float* __restrict__ Wb, float* __restrict__ Cb,
    int M, int N, int K, long long sA, long long sW, long long sC,
    const float* __restrict__ cw, const float* __restrict__ qw,
    const float* __restrict__ bvec)
{
    const int z = blockIdx.z;
    const float* A = Ab + (size_t)z * sA;
    const float* W = Wb + (size_t)z * sW;
    float* C = Cb + (size_t)z * sC;
    const int m0 = blockIdx.y * 128, n0 = blockIdx.x * 64;
    __shared__ float As[16][128];
    __shared__ float Bs[16][64];
    const int tid = threadIdx.x;
    const int tx = tid & 15, ty = tid >> 4;
    float acc[8][4];
#pragma unroll
    for (int i = 0; i < 8; i++)
#pragma unroll
        for (int j = 0; j < 4; j++) acc[i][j] = 0.f;

    for (int k0 = 0; k0 < K; k0 += 16) {
#pragma unroll
        for (int l = 0; l < 2; l++) {
            int slot = tid * 2 + l;
            int row = slot >> 2, kc = (slot & 3) << 2;
            float4 v = *(const float4*)(A + (size_t)(m0 + row) * K + k0 + kc);
            As[kc][row] = v.x; As[kc+1][row] = v.y; As[kc+2][row] = v.z; As[kc+3][row] = v.w;
        }
        {
            int nr = tid >> 2, kc = (tid & 3) << 2;
            float4 v = *(const float4*)(W + (size_t)(n0 + nr) * K + k0 + kc);
            Bs[kc][nr] = v.x; Bs[kc+1][nr] = v.y; Bs[kc+2][nr] = v.z; Bs[kc+3][nr] = v.w;
        }
        __syncthreads();
#pragma unroll
        for (int k = 0; k < 16; k++) {
            float4 a0 = *(float4*)&As[k][ty*8];
            float4 a1 = *(float4*)&As[k][ty*8+4];
            float4 b0 = *(float4*)&Bs[k][tx*4];
            float av[8] = {a0.x,a0.y,a0.z,a0.w,a1.x,a1.y,a1.z,a1.w};
            float bv[4] = {b0.x,b0.y,b0.z,b0.w};
#pragma unroll
            for (int i = 0; i < 8; i++)
#pragma unroll
                for (int j = 0; j < 4; j++) acc[i][j] += av[i] * bv[j];
        }
        __syncthreads();
    }
    float badd = bvec[0] + bvec[1] + bvec[2];
#pragma unroll
    for (int i = 0; i < 8; i++) {
        int m = m0 + ty*8 + i;
#pragma unroll
        for (int j = 0; j < 4; j++) {
            int n = n0 + tx*4 + j;
            C[(size_t)m * N + n] = acc[i][j] + cw[(size_t)z * TT + m] + qw[(size_t)z * TT + n] + badd;
        }
    }
}

// ---------------- c2q GEMM + full BiDAF epilogue ----------------
__global__ void __launch_bounds__(256) gemm_c2q(
    const float* __restrict__ Ab, const float* __restrict__ Bb, long long sB,
    const float* __restrict__ cb, long long sCrow,
    float* __restrict__ outb, int addMode)
{
    const int z = blockIdx.z;
    const float* A = Ab + (size_t)z * TT * TT;
    const float* B = Bb + (size_t)z * sB;
    const float* c = cb + (size_t)z * sCrow;
    const float* qc = g_q2c + (size_t)z * D2;
    float* out = outb + (size_t)z * TT * D8;
    const int m0 = blockIdx.y * 128, n0 = blockIdx.x * 64;
    __shared__ float As[16][128];
    __shared__ float Bs[16][64];
    const int tid = threadIdx.x;
    const int tx = tid & 15, ty = tid >> 4;
    float acc[8][4];
#pragma unroll
    for (int i = 0; i < 8; i++)
#pragma unroll
        for (int j = 0; j < 4; j++) acc[i][j] = 0.f;

    for (int k0 = 0; k0 < TT; k0 += 16) {
#pragma unroll
        for (int l = 0; l < 2; l++) {
            int slot = tid * 2 + l;
            int row = slot >> 2, kc = (slot & 3) << 2;
            float4 v = *(const float4*)(A + (size_t)(m0 + row) * TT + k0 + kc);
            As[kc][row] = v.x; As[kc+1][row] = v.y; As[kc+2][row] = v.z; As[kc+3][row] = v.w;
        }
        {
            int kr = tid >> 4, nc = (tid & 15) << 2;
            *(float4*)&Bs[kr][nc] = *(const float4*)(B + (size_t)(k0 + kr) * D2 + n0 + nc);
        }
        __syncthreads();
#pragma unroll
        for (int k = 0; k < 16; k++) {
            float4 a0 = *(float4*)&As[k][ty*8];
            float4 a1 = *(float4*)&As[k][ty*8+4];
            float4 b0 = *(float4*)&Bs[k][tx*4];
            float av[8] = {a0.x,a0.y,a0.z,a0.w,a1.x,a1.y,a1.z,a1.w};
            float bv[4] = {b0.x,b0.y,b0.z,b0.w};
#pragma unroll
            for (int i = 0; i < 8; i++)
#pragma unroll
                for (int j = 0; j < 4; j++) acc[i][j] += av[i] * bv[j];
        }
        __syncthreads();
    }
#pragma unroll
    for (int i = 0; i < 8; i++) {
        int m = m0 + ty*8 + i;
#pragma unroll
        for (int j = 0; j < 4; j++) {
            int n = n0 + tx*4 + j;
            float cv = c[(size_t)m * D2 + n];
            float c2 = acc[i][j];
            float o0 = fmaxf(cv, 0.f);
            float o1 = fmaxf(c2, 0.f);
            float o2 = fmaxf(cv * c2, 0.f);
            float o3 = fmaxf(cv * qc[n], 0.f);
            size_t b = (size_t)m * D8 + n;
            if (addMode) {
                out[b] += o0; out[b+512] += o1; out[b+1024] += o2; out[b+1536] += o3;
            } else {
                out[b] = o0; out[b+512] = o1; out[b+1024] = o2; out[b+1536] = o3;
            }
        }
    }
}

// ---------------- persistent GRU scan (cluster-8) ----------------
#define WS_STRIDE 257
#define WS_FLOATS (96 * WS_STRIDE)
#define HS_FLOATS (2 * 16 * 256)
#define SCAN_SMEM ((WS_FLOATS + HS_FLOATS) * 4)

__global__ void __cluster_dims__(8, 1, 1) __launch_bounds__(256)
gru_scan(const float* __restrict__ gi, const float* __restrict__ whh,
         const float* __restrict__ bhh, float* __restrict__ seqout, int S)
{
    extern __shared__ float smf[];
    float* ws  = smf;
    float* hsb = smf + WS_FLOATS;

    const int tid = threadIdx.x;
    const int tx = tid & 31, tg = tid >> 5;
    const int j0 = blockIdx.x * 32;
    const int m0 = blockIdx.y * 16;
    const int dd = m0 / S;
    const int j = j0 + tx;
    const int r0 = tg * 2;

    const float* wb = whh + (size_t)dd * G3 * HIDN;
    for (int idx = tid; idx < 96 * 64; idx += 256) {
        int row = idx >> 6;
        int kq = (idx & 63) << 2;
        int g = row >> 5, cc = row & 31;
        float4 v = *(const float4*)(wb + (size_t)(g * 256 + j0 + cc) * HIDN + kq);
        float* d = ws + row * WS_STRIDE + kq;
        d[0] = v.x; d[1] = v.y; d[2] = v.z; d[3] = v.w;
    }
    for (int i = tid; i < 16 * 256; i += 256) hsb[i] = 0.f;

    const float b0 = bhh[(size_t)dd * G3 + j];
    const float b1 = bhh[(size_t)dd * G3 + 256 + j];
    const float b2 = bhh[(size_t)dd * G3 + 512 + j];

    const int mA = m0 + r0, mB = m0 + r0 + 1;
    const int sA = mA - dd * S, sB = mB - dd * S;
    const size_t giA = ((size_t)(dd * S + sA)) * TT * G3;
    const size_t giB = ((size_t)(dd * S + sB)) * TT * G3;

    const float* w0p = ws + (size_t)tx * WS_STRIDE;
    const float* w1p = ws + (size_t)(32 + tx) * WS_STRIDE;
    const float* w2p = ws + (size_t)(64 + tx) * WS_STRIDE;

    cluster_sync_();

    for (int t = 0; t < TT; t++) {
        const float* hc = hsb + (t & 1) * 4096;
        float* hn = hsb + ((t + 1) & 1) * 4096;
        const float* hA = hc + r0 * 256;
        const float* hB = hc + (r0 + 1) * 256;

        float a00 = 0.f, a01 = 0.f, a02 = 0.f;
        float a10 = 0.f, a11 = 0.f, a12 = 0.f;
#pragma unroll 2
        for (int k = 0; k < 256; k += 4) {
            float4 h0v = *(const float4*)(hA + k);
            float4 h1v = *(const float4*)(hB + k);
#pragma unroll
            for (int u = 0; u < 4; u++) {
                float h0 = (&h0v.x)[u], h1 = (&h1v.x)[u];
                float w0 = w0p[k + u], w1 = w1p[k + u], w2 = w2p[k + u];
                a00 += h0 * w0; a01 += h0 * w1; a02 += h0 * w2;
                a10 += h1 * w0; a11 += h1 * w1; a12 += h1 * w2;
            }
        }

        const int tq = dd ? (TT - 1 - t) : t;
#pragma unroll
        for (int r = 0; r < 2; r++) {
            size_t gb = (r ? giB : giA) + (size_t)tq * G3;
            float ir  = gi[gb + j];
            float iz  = gi[gb + 256 + j];
            float inn = gi[gb + 512 + j];
            float g0 = r ? a10 : a00;
            float g1 = r ? a11 : a01;
            float g2 = r ? a12 : a02;
            float rg = sigm(ir + g0 + b0);
            float zg = sigm(iz + g1 + b1);
            float ng = tanhf(inn + rg * (g2 + b2));
            float hold = hc[(r0 + r) * 256 + j];
            float hnew = (1.f - zg) * ng + zg * hold;
            int s = r ? sB : sA;
            seqout[((size_t)s * TT + tq) * D2 + dd * HIDN + j] = hnew;
            uint32_t la = (uint32_t)__cvta_generic_to_shared(&hn[(r0 + r) * 256 + j]);
#pragma unroll
            for (int rk = 0; rk < 8; rk++) sts_remote(la, rk, hnew);
        }
        cluster_sync_();
    }
}

// ---------------- BiDAF prep / softmax / q2c / rank ----------------
__global__ void __launch_bounds__(256) bidaf_prep(
    const float* __restrict__ cbase, const float* __restrict__ qbase,
    const float* __restrict__ w)
{
    __shared__ float red[256];
    int i = blockIdx.x, z = blockIdx.y, tid = threadIdx.x;
    const float* c = cbase + ((size_t)z * TT + i) * D2;
    const float* q = qbase + ((size_t)z * TT + i) * D2;
    float c0 = c[tid], c1 = c[tid + 256];
    float q0 = q[tid], q1 = q[tid + 256];
    float sc = c0 * w[tid] + c1 * w[tid + 256];
    float sq = q0 * w[512 + tid] + q1 * w[768 + tid];
    float* csc = g_csc + ((size_t)z * TT + i) * D2;
    csc[tid]       = c0 * w[1024 + tid];
    csc[tid + 256] = c1 * w[1280 + tid];
    float rc = blk_sum(sc, red);
    float rq = blk_sum(sq, red);
    if (tid == 0) { g_cw[z * TT + i] = rc; g_qw[z * TT + i] = rq; }
}

__global__ void __launch_bounds__(256) softmax_row()
{
    __shared__ float red[256];
    int i = blockIdx.x, z = blockIdx.y, tid = threadIdx.x;
    float* row = g_Sc + ((size_t)z * TT + i) * TT;
    float v = row[tid];
    float mx = blk_max(v, red);
    float e = __expf(v - mx);
    float sm = blk_sum(e, red);
    row[tid] = e / sm;
    if (tid == 0) g_mrow[z * TT + i] = mx;
}

__global__ void __launch_bounds__(256) q2c_kern(const float* __restrict__ cbase)
{
    __shared__ float red[256];
    __shared__ float bbuf[256];
    int z = blockIdx.x, tid = threadIdx.x;
    float v = g_mrow[z * TT + tid];
    float mx = blk_max(v, red);
    float e = __expf(v - mx);
    float sm = blk_sum(e, red);
    bbuf[tid] = e / sm;
    __syncthreads();
    const float* c = cbase + (size_t)z * TT * D2;
    float a0 = 0.f, a1 = 0.f;
    for (int i = 0; i < TT; i++) {
        float b = bbuf[i];
        a0 += b * c[(size_t)i * D2 + tid];
        a1 += b * c[(size_t)i * D2 + tid + 256];
    }
    g_q2c[(size_t)z * D2 + tid] = a0;
    g_q2c[(size_t)z * D2 + tid + 256] = a1;
}

__global__ void __launch_bounds__(256) rank_partial(const float* __restrict__ rw)
{
    __shared__ float red[256];
    int chunk = blockIdx.x, bo = blockIdx.y, tid = threadIdx.x;
    const float* s0 = g_att + (size_t)(bo * 2) * TT * D8;
    const float* s1 = g_att + (size_t)(bo * 2 + 1) * TT * D8;
    float acc = 0.f;
    int e0 = chunk * 8192 + tid;
#pragma unroll 4
    for (int it = 0; it < 32; it++) {
        int e = e0 + it * 256;
        acc += fmaxf(s0[e], s1[e]) * rw[e];
    }
    float r = blk_sum(acc, red);
    if (tid == 0) g_part[bo * 64 + chunk] = r;
}

__global__ void rank_final(const float* __restrict__ rb, float* __restrict__ out)
{
    __shared__ float red[64];
    int bo = blockIdx.x, tid = threadIdx.x;
    red[tid] = g_part[bo * 64 + tid];
    __syncthreads();
    for (int o = 32; o > 0; o >>= 1) {
        if (tid < o) red[tid] += red[tid + o];
        __syncthreads();
    }
    if (tid == 0) out[bo] = red[0] + rb[0];
}

// ---------------- host ----------------
extern "C" void kernel_launch(void* const* d_in, const int* in_sizes, int n_in,
                              void* d_out, int out_size)
{
    const int*   question = (const int*)d_in[0];
    const int*   article  = (const int*)d_in[1];
    const float* emb      = (const float*)d_in[2];
    const float* g1_wih   = (const float*)d_in[3];
    const float* g1_whh   = (const float*)d_in[4];
    const float* g1_bih   = (const float*)d_in[5];
    const float* g1_bhh   = (const float*)d_in[6];
    const float* g2_wih   = (const float*)d_in[7];
    const float* g2_whh   = (const float*)d_in[8];
    const float* g2_bih   = (const float*)d_in[9];
    const float* g2_bhh   = (const float*)d_in[10];
    const float* b1_w     = (const float*)d_in[11];
    const float* b1_b     = (const float*)d_in[12];
    const float* b2_w     = (const float*)d_in[13];
    const float* b2_b     = (const float*)d_in[14];
    const float* rank_w   = (const float*)d_in[15];
    const float* rank_b   = (const float*)d_in[16];
    float* out = (float*)d_out;

    float *xcat, *gi1, *gi2, *hcat, *h2out, *att, *csc, *Sc, *cwp, *qwp;
    cudaGetSymbolAddress((void**)&xcat, g_xcat);
    cudaGetSymbolAddress((void**)&gi1,  g_gi1);
    cudaGetSymbolAddress((void**)&gi2,  g_gi2);
    cudaGetSymbolAddress((void**)&hcat, g_hcat);
    cudaGetSymbolAddress((void**)&h2out,g_h2out);
    cudaGetSymbolAddress((void**)&att,  g_att);
    cudaGetSymbolAddress((void**)&csc,  g_csc);
    cudaGetSymbolAddress((void**)&Sc,   g_Sc);
    cudaGetSymbolAddress((void**)&cwp,  g_cw);
    cudaGetSymbolAddress((void**)&qwp,  g_qw);

    cudaFuncSetAttribute(gru_scan, cudaFuncAttributeMaxDynamicSharedMemorySize, SCAN_SMEM);

    // 1. embed
    gather_embed<<<dim3(TT, S1), 256>>>(question, article, emb);

    // 2. gi1 = xcat @ wih1^T + bih1 (tensor cores, split-bf16 mma.sync)
    gemm_mma<<<dim3(G3/64, (S1*TT)/128, 2), 256>>>(
        xcat, g1_wih, gi1, g1_bih, S1*TT, HIDN);

    // 3. layer-1 scan
    gru_scan<<<dim3(8, M1/16), 256, SCAN_SMEM>>>(gi1, g1_whh, g1_bhh, hcat, S1);

    // 4. BiDAF1
    const float* cb1 = hcat;
    const float* qb1 = hcat + (size_t)64 * TT * D2;
    bidaf_prep<<<dim3(TT, S2), 256>>>(cb1, qb1, b1_w);
    gemm_awt<<<dim3(TT/64, TT/128, S2), 256>>>(
        csc, qb1, Sc, TT, TT, D2,
        (long long)TT*D2, (long long)TT*D2, (long long)TT*TT,
        cwp, qwp, b1_b);
    softmax_row<<<dim3(TT, S2), 256>>>();
    q2c_kern<<<S2, 256>>>(cb1);
    gemm_c2q<<<dim3(D2/64, TT/128, S2), 256>>>(
        Sc, qb1, (long long)TT*D2, cb1, (long long)TT*D2, att, 0);

    // 5. gi2 = att @ wih2^T + bih2 (tensor cores)
    gemm_mma<<<dim3(G3/64, (S2*TT)/128, 2), 256>>>(
        att, g2_wih, gi2, g2_bih, S2*TT, D8);

    // 6. layer-2 scan
    gru_scan<<<dim3(8, M2/16), 256, SCAN_SMEM>>>(gi2, g2_whh, g2_bhh, h2out, S2);

    // 7. BiDAF2 (accumulate into att)
    bidaf_prep<<<dim3(TT, S2), 256>>>(h2out, h2out, b2_w);
    gemm_awt<<<dim3(TT/64, TT/128, S2), 256>>>(
        csc, h2out, Sc, TT, TT, D2,
        (long long)TT*D2, (long long)TT*D2, (long long)TT*TT,
        cwp, qwp, b2_b);
    softmax_row<<<dim3(TT, S2), 256>>>();
    q2c_kern<<<S2, 256>>>(h2out);
    gemm_c2q<<<dim3(D2/64, TT/128, S2), 256>>>(
        Sc, h2out, (long long)TT*D2, h2out, (long long)TT*D2, att, 1);

    // 8. rank
    rank_partial<<<dim3(64, 32), 256>>>(rank_w);
    rank_final<<<32, 64>>>(rank_b, out);
}

// round 7
// speedup vs baseline: 2.2554x; 1.6571x over previous
#include <cuda_runtime.h>
#include <cuda_bf16.h>
#include <math.h>
#include <stdint.h>

#define TT 256
#define HIDN 256
#define G3 768
#define D2 512
#define D8 2048
#define S1 128
#define S2 64
#define M1 256
#define M2 128

// ---------------- static device scratch ----------------
__device__ float g_xcat [(size_t)S1*TT*HIDN];
__device__ float g_gi1  [(size_t)2*S1*TT*G3];
__device__ float g_hcat [(size_t)S1*TT*D2];
__device__ float g_h2out[(size_t)S2*TT*D2];
__device__ float g_gi2  [(size_t)2*S2*TT*G3];
__device__ float g_att  [(size_t)S2*TT*D8];
__device__ float g_csc  [(size_t)S2*TT*D2];
__device__ float g_Sc   [(size_t)S2*TT*TT];
__device__ float g_cw   [S2*TT];
__device__ float g_qw   [S2*TT];
__device__ float g_mrow [S2*TT];
__device__ float g_q2c  [S2*D2];
__device__ float g_part [32*64];

// ---------------- generic helpers ----------------
__device__ __forceinline__ float blk_sum(float v, float* red) {
    int t = threadIdx.x;
    red[t] = v; __syncthreads();
    for (int o = blockDim.x >> 1; o > 0; o >>= 1) {
        if (t < o) red[t] += red[t + o];
        __syncthreads();
    }
    float r = red[0]; __syncthreads();
    return r;
}
__device__ __forceinline__ float blk_max(float v, float* red) {
    int t = threadIdx.x;
    red[t] = v; __syncthreads();
    for (int o = blockDim.x >> 1; o > 0; o >>= 1) {
        if (t < o) red[t] = fmaxf(red[t], red[t + o]);
        __syncthreads();
    }
    float r = red[0]; __syncthreads();
    return r;
}
__device__ __forceinline__ float sigm(float x) { return 1.f / (1.f + __expf(-x)); }

__device__ __forceinline__ void cluster_sync_() {
    asm volatile("barrier.cluster.arrive.aligned;" ::: "memory");
    asm volatile("barrier.cluster.wait.aligned;" ::: "memory");
}

// ---------------- embedding gather ----------------
__global__ void __launch_bounds__(256) gather_embed(
    const int* __restrict__ q, const int* __restrict__ a,
    const float* __restrict__ emb)
{
    int t = blockIdx.x, s = blockIdx.y, tid = threadIdx.x;
    int id = (s < 64) ? q[(s >> 1) * TT + t] : a[(size_t)(s - 64) * TT + t];
    g_xcat[((size_t)s * TT + t) * HIDN + tid] = emb[(size_t)id * HIDN + tid];
}

// ---------------- split-bf16 helpers ----------------
__device__ __forceinline__ uint32_t pk2(__nv_bfloat16 a, __nv_bfloat16 b) {
    return (uint32_t)__bfloat16_as_ushort(a) | ((uint32_t)__bfloat16_as_ushort(b) << 16);
}
__device__ __forceinline__ void split8(const float* f, uint4& hi, uint4& lo) {
    __nv_bfloat16 h[8]; float l[8];
#pragma unroll
    for (int i = 0; i < 8; i++) {
        h[i] = __float2bfloat16(f[i]);
        l[i] = f[i] - __bfloat162float(h[i]);
    }
    hi = make_uint4(pk2(h[0],h[1]), pk2(h[2],h[3]), pk2(h[4],h[5]), pk2(h[6],h[7]));
    lo = make_uint4(pk2(__float2bfloat16(l[0]),__float2bfloat16(l[1])),
                    pk2(__float2bfloat16(l[2]),__float2bfloat16(l[3])),
                    pk2(__float2bfloat16(l[4]),__float2bfloat16(l[5])),
                    pk2(__float2bfloat16(l[6]),__float2bfloat16(l[7])));
}

#define LDMX4(r0,r1,r2,r3,addr) \
    asm volatile("ldmatrix.sync.aligned.m8n8.x4.shared.b16 {%0,%1,%2,%3}, [%4];" \
        : "=r"(r0), "=r"(r1), "=r"(r2), "=r"(r3) : "r"(addr))

#define MMA16816(c0,c1,c2,c3,a0,a1,a2,a3,b0,b1) \
    asm volatile("mma.sync.aligned.m16n8k16.row.col.f32.bf16.bf16.f32 " \
        "{%0,%1,%2,%3}, {%4,%5,%6,%7}, {%8,%9}, {%0,%1,%2,%3};" \
        : "+f"(c0), "+f"(c1), "+f"(c2), "+f"(c3) \
        : "r"(a0), "r"(a1), "r"(a2), "r"(a3), "r"(b0), "r"(b1))

// ---------------- mma.sync split-bf16 GEMM: C = A * W^T + bias ----------------
#define SKP 40
__global__ void __launch_bounds__(256) gemm_mma(
    const float* __restrict__ Ab, const float* __restrict__ Wb,
    float* __restrict__ Cb, const float* __restrict__ biasb,
    int M, int K)
{
    __shared__ __nv_bfloat16 As[2][128][SKP];
    __shared__ __nv_bfloat16 Bs[2][64][SKP];
    const int tid = threadIdx.x;
    const int wid = tid >> 5, lane = tid & 31;
    const int z = blockIdx.z;
    const int m0 = blockIdx.y * 128, n0 = blockIdx.x * 64;
    const float* A = Ab;
    const float* W = Wb + (size_t)z * G3 * K;
    float* C = Cb + (size_t)z * (size_t)M * G3;
    const float* bias = biasb + (size_t)z * G3;

    const int wm = (wid & 3) * 32;
    const int wn = (wid >> 2) * 32;

    float acc[2][4][4];
#pragma unroll
    for (int i = 0; i < 2; i++)
#pragma unroll
        for (int j = 0; j < 4; j++)
#pragma unroll
            for (int q = 0; q < 4; q++) acc[i][j][q] = 0.f;

    const int lrow = ((lane >> 3) & 1) * 8 + (lane & 7);
    const int lk8 = (lane >> 4) * 8;

    for (int k0 = 0; k0 < K; k0 += 32) {
#pragma unroll
        for (int it = 0; it < 2; it++) {
            int gidx = tid + it * 256;
            int r = gidx >> 2, cg = gidx & 3;
            const float* src = A + (size_t)(m0 + r) * K + k0 + cg * 8;
            float f[8];
            *(float4*)&f[0] = *(const float4*)src;
            *(float4*)&f[4] = *(const float4*)(src + 4);
            uint4 hi, lo; split8(f, hi, lo);
            *(uint4*)&As[0][r][cg * 8] = hi;
            *(uint4*)&As[1][r][cg * 8] = lo;
        }
        {
            int r = tid >> 2, cg = tid & 3;
            const float* src = W + (size_t)(n0 + r) * K + k0 + cg * 8;
            float f[8];
            *(float4*)&f[0] = *(const float4*)src;
            *(float4*)&f[4] = *(const float4*)(src + 4);
            uint4 hi, lo; split8(f, hi, lo);
            *(uint4*)&Bs[0][r][cg * 8] = hi;
            *(uint4*)&Bs[1][r][cg * 8] = lo;
        }
        __syncthreads();
#pragma unroll
        for (int kk = 0; kk < 32; kk += 16) {
            uint32_t aF[2][2][4], bF[2][2][4];
#pragma unroll
            for (int s = 0; s < 2; s++) {
#pragma unroll
                for (int mi = 0; mi < 2; mi++) {
                    uint32_t ad = (uint32_t)__cvta_generic_to_shared(
                        &As[s][wm + mi * 16 + lrow][kk + lk8]);
                    LDMX4(aF[s][mi][0], aF[s][mi][1], aF[s][mi][2], aF[s][mi][3], ad);
                }
#pragma unroll
                for (int nj2 = 0; nj2 < 2; nj2++) {
                    uint32_t ad = (uint32_t)__cvta_generic_to_shared(
                        &Bs[s][wn + nj2 * 16 + lrow][kk + lk8]);
                    LDMX4(bF[s][nj2][0], bF[s][nj2][1], bF[s][nj2][2], bF[s][nj2][3], ad);
                }
            }
#pragma unroll
            for (int term = 0; term < 3; term++) {
                const int sa = (term == 2) ? 1 : 0;
                const int sb = (term == 1) ? 1 : 0;
#pragma unroll
                for (int mi = 0; mi < 2; mi++)
#pragma unroll
                    for (int nj = 0; nj < 4; nj++) {
                        int nj2 = nj >> 1, odd = nj & 1;
                        MMA16816(acc[mi][nj][0], acc[mi][nj][1], acc[mi][nj][2], acc[mi][nj][3],
                                 aF[sa][mi][0], aF[sa][mi][1], aF[sa][mi][2], aF[sa][mi][3],
                                 bF[sb][nj2][odd], bF[sb][nj2][2 + odd]);
                    }
            }
        }
        __syncthreads();
    }
    const int g = lane >> 2, t4 = lane & 3;
#pragma unroll
    for (int mi = 0; mi < 2; mi++) {
        int mrow = m0 + wm + mi * 16 + g;
#pragma unroll
        for (int nj = 0; nj < 4; nj++) {
            int ncol = n0 + wn + nj * 8 + t4 * 2;
            float b0v = bias[ncol], b1v = bias[ncol + 1];
            float2 v0 = make_float2(acc[mi][nj][0] + b0v, acc[mi][nj][1] + b1v);
            float2 v1 = make_float2(acc[mi][nj][2] + b0v, acc[mi][nj][3] + b1v);
            *(float2*)&C[(size_t)mrow * G3 + ncol] = v0;
            *(float2*)&C[(size_t)(mrow + 8) * G3 + ncol] = v1;
        }
    }
}

// ---------------- SIMT GEMM (BiDAF scores) ----------------
__global__ void __launch_bounds__(256) gemm_awt(
    const float* __restrict__ Ab, const float* __restrict__ Wb, float* __restrict__ Cb,
    int M, int N, int K, long long sA, long long sW, long long sC,
    const float* __restrict__ cw, const float* __restrict__ qw,
    const float* __restrict__ bvec)
{
    const int z = blockIdx.z;
    const float* A = Ab + (size_t)z * sA;
    const float* W = Wb + (size_t)z * sW;
    float* C = Cb + (size_t)z * sC;
    const int m0 = blockIdx.y * 128, n0 = blockIdx.x * 64;
    __shared__ float As[16][128];
    __shared__ float Bs[16][64];
    const int tid = threadIdx.x;
    const int tx = tid & 15, ty = tid >> 4;
    float acc[8][4];
#pragma unroll
    for (int i = 0; i < 8; i++)
#pragma unroll
        for (int j = 0; j < 4; j++) acc[i][j] = 0.f;

    for (int k0 = 0; k0 < K; k0 += 16) {
#pragma unroll
        for (int l = 0; l < 2; l++) {
            int slot = tid * 2 + l;
            int row = slot >> 2, kc = (slot & 3) << 2;
            float4 v = *(const float4*)(A + (size_t)(m0 + row) * K + k0 + kc);
            As[kc][row] = v.x; As[kc+1][row] = v.y; As[kc+2][row] = v.z; As[kc+3][row] = v.w;
        }
        {
            int nr = tid >> 2, kc = (tid & 3) << 2;
            float4 v = *(const float4*)(W + (size_t)(n0 + nr) * K + k0 + kc);
            Bs[kc][nr] = v.x; Bs[kc+1][nr] = v.y; Bs[kc+2][nr] = v.z; Bs[kc+3][nr] = v.w;
        }
        __syncthreads();
#pragma unroll
        for (int k = 0; k < 16; k++) {
            float4 a0 = *(float4*)&As[k][ty*8];
            float4 a1 = *(float4*)&As[k][ty*8+4];
            float4 b0 = *(float4*)&Bs[k][tx*4];
            float av[8] = {a0.x,a0.y,a0.z,a0.w,a1.x,a1.y,a1.z,a1.w};
            float bv[4] = {b0.x,b0.y,b0.z,b0.w};
#pragma unroll
            for (int i = 0; i < 8; i++)
#pragma unroll
                for (int j = 0; j < 4; j++) acc[i][j] += av[i] * bv[j];
        }
        __syncthreads();
    }
    float badd = bvec[0] + bvec[1] + bvec[2];
#pragma unroll
    for (int i = 0; i < 8; i++) {
        int m = m0 + ty*8 + i;
#pragma unroll
        for (int j = 0; j < 4; j++) {
            int n = n0 + tx*4 + j;
            C[(size_t)m * N + n] = acc[i][j] + cw[(size_t)z * TT + m] + qw[(size_t)z * TT + n] + badd;
        }
    }
}

// ---------------- c2q GEMM + full BiDAF epilogue ----------------
__global__ void __launch_bounds__(256) gemm_c2q(
    const float* __restrict__ Ab, const float* __restrict__ Bb, long long sB,
    const float* __restrict__ cb, long long sCrow,
    float* __restrict__ outb, int addMode)
{
    const int z = blockIdx.z;
    const float* A = Ab + (size_t)z * TT * TT;
    const float* B = Bb + (size_t)z * sB;
    const float* c = cb + (size_t)z * sCrow;
    const float* qc = g_q2c + (size_t)z * D2;
    float* out = outb + (size_t)z * TT * D8;
    const int m0 = blockIdx.y * 128, n0 = blockIdx.x * 64;
    __shared__ float As[16][128];
    __shared__ float Bs[16][64];
    const int tid = threadIdx.x;
    const int tx = tid & 15, ty = tid >> 4;
    float acc[8][4];
#pragma unroll
    for (int i = 0; i < 8; i++)
#pragma unroll
        for (int j = 0; j < 4; j++) acc[i][j] = 0.f;

    for (int k0 = 0; k0 < TT; k0 += 16) {
#pragma unroll
        for (int l = 0; l < 2; l++) {
            int slot = tid * 2 + l;
            int row = slot >> 2, kc = (slot & 3) << 2;
            float4 v = *(const float4*)(A + (size_t)(m0 + row) * TT + k0 + kc);
            As[kc][row] = v.x; As[kc+1][row] = v.y; As[kc+2][row] = v.z; As[kc+3][row] = v.w;
        }
        {
            int kr = tid >> 4, nc = (tid & 15) << 2;
            *(float4*)&Bs[kr][nc] = *(const float4*)(B + (size_t)(k0 + kr) * D2 + n0 + nc);
        }
        __syncthreads();
#pragma unroll
        for (int k = 0; k < 16; k++) {
            float4 a0 = *(float4*)&As[k][ty*8];
            float4 a1 = *(float4*)&As[k][ty*8+4];
            float4 b0 = *(float4*)&Bs[k][tx*4];
            float av[8] = {a0.x,a0.y,a0.z,a0.w,a1.x,a1.y,a1.z,a1.w};
            float bv[4] = {b0.x,b0.y,b0.z,b0.w};
#pragma unroll
            for (int i = 0; i < 8; i++)
#pragma unroll
                for (int j = 0; j < 4; j++) acc[i][j] += av[i] * bv[j];
        }
        __syncthreads();
    }
#pragma unroll
    for (int i = 0; i < 8; i++) {
        int m = m0 + ty*8 + i;
#pragma unroll
        for (int j = 0; j < 4; j++) {
            int n = n0 + tx*4 + j;
            float cv = c[(size_t)m * D2 + n];
            float c2 = acc[i][j];
            float o0 = fmaxf(cv, 0.f);
            float o1 = fmaxf(c2, 0.f);
            float o2 = fmaxf(cv * c2, 0.f);
            float o3 = fmaxf(cv * qc[n], 0.f);
            size_t b = (size_t)m * D8 + n;
            if (addMode) {
                out[b] += o0; out[b+512] += o1; out[b+1024] += o2; out[b+1536] += o3;
            } else {
                out[b] = o0; out[b+512] = o1; out[b+1024] = o2; out[b+1536] = o3;
            }
        }
    }
}

// ---------------- tensor-core persistent GRU scan (cluster-8) ----------------
// CTA: j-tile of 32 (96 gate rows), cluster covers 8 j-tiles of one 16-stream group.
// B (whh slice) bf16 hi/lo in smem once; h as bf16 hi/lo double-buffered, broadcast
// via DSMEM u16 stores. Warps 0-5: mma; warps 6-7: gi prefetch.
#define ABST 264                   // halves per row for A and B smem
#define ABUF (16 * ABST)           // elems per A sub-buffer
#define OFF_BHI 0
#define OFF_BLO (96 * ABST * 2)
#define OFF_A   (OFF_BLO + 96 * ABST * 2)          // 4 sub-buffers: (buf*2+hi/lo)
#define OFF_GHS (OFF_A + 4 * ABUF * 2)
#define OFF_GIS (OFF_GHS + 16 * 104 * 4)
#define SCAN2_SMEM (OFF_GIS + 16 * 104 * 4)

__global__ void __cluster_dims__(8, 1, 1) __launch_bounds__(256)
gru_scan_mma(const float* __restrict__ gi, const float* __restrict__ whh,
             const float* __restrict__ bhh, float* __restrict__ seqout, int S)
{
    extern __shared__ char smraw[];
    __nv_bfloat16* Bhi = (__nv_bfloat16*)(smraw + OFF_BHI);
    __nv_bfloat16* Blo = (__nv_bfloat16*)(smraw + OFF_BLO);
    __nv_bfloat16* Ab  = (__nv_bfloat16*)(smraw + OFF_A);
    float* ghs = (float*)(smraw + OFF_GHS);
    float* gis = (float*)(smraw + OFF_GIS);

    const int tid = threadIdx.x;
    const int wid = tid >> 5, lane = tid & 31;
    const int j0 = blockIdx.x * 32;
    const int m0 = blockIdx.y * 16;
    const int dd = m0 / S;
    const int jj = tid & 31, j = j0 + jj;
    const int r0 = (tid >> 5) * 2;

    // load + split whh slice once: row = g*32+cc <-> whh row g*256+j0+cc
    const float* wb = whh + (size_t)dd * G3 * HIDN;
    for (int task = tid; task < 96 * 32; task += 256) {
        int row = task >> 5, grp = task & 31;
        int g = row >> 5, cc = row & 31;
        const float* src = wb + (size_t)(g * 256 + j0 + cc) * HIDN + grp * 8;
        float f[8];
        *(float4*)&f[0] = *(const float4*)src;
        *(float4*)&f[4] = *(const float4*)(src + 4);
        uint4 hi, lo; split8(f, hi, lo);
        *(uint4*)&Bhi[row * ABST + grp * 8] = hi;
        *(uint4*)&Blo[row * ABST + grp * 8] = lo;
    }
    // zero all 4 A sub-buffers
    for (int i = tid; i < 4 * ABUF / 2; i += 256)
        ((uint32_t*)Ab)[i] = 0;

    const float b0 = bhh[(size_t)dd * G3 + j];
    const float b1 = bhh[(size_t)dd * G3 + 256 + j];
    const float b2 = bhh[(size_t)dd * G3 + 512 + j];

    // mapa bases for the 8 cluster ranks (byte addresses of A region)
    uint32_t abase = (uint32_t)__cvta_generic_to_shared(Ab);
    uint32_t peer[8];
#pragma unroll
    for (int rk = 0; rk < 8; rk++)
        asm volatile("mapa.shared::cluster.u32 %0, %1, %2;" : "=r"(peer[rk]) : "r"(abase), "r"(rk));

    const int lrow = ((lane >> 3) & 1) * 8 + (lane & 7);
    const int lk8 = (lane >> 4) * 8;

    cluster_sync_();

    for (int t = 0; t < TT; t++) {
        const int cur = t & 1, nxt = cur ^ 1;
        const int tq = dd ? (TT - 1 - t) : t;

        if (wid < 6) {
            const __nv_bfloat16* Ahi = Ab + (cur * 2 + 0) * ABUF;
            const __nv_bfloat16* Alo = Ab + (cur * 2 + 1) * ABUF;
            float acc[2][4] = {{0,0,0,0},{0,0,0,0}};
#pragma unroll
            for (int kt = 0; kt < 16; kt++) {
                uint32_t aF[2][4], bF[2][4];
                uint32_t adh = (uint32_t)__cvta_generic_to_shared(
                    &Ahi[lrow * ABST + kt * 16 + lk8]);
                uint32_t adl = (uint32_t)__cvta_generic_to_shared(
                    &Alo[lrow * ABST + kt * 16 + lk8]);
                LDMX4(aF[0][0], aF[0][1], aF[0][2], aF[0][3], adh);
                LDMX4(aF[1][0], aF[1][1], aF[1][2], aF[1][3], adl);
                uint32_t bdh = (uint32_t)__cvta_generic_to_shared(
                    &Bhi[(wid * 16 + lrow) * ABST + kt * 16 + lk8]);
                uint32_t bdl = (uint32_t)__cvta_generic_to_shared(
                    &Blo[(wid * 16 + lrow) * ABST + kt * 16 + lk8]);
                LDMX4(bF[0][0], bF[0][1], bF[0][2], bF[0][3], bdh);
                LDMX4(bF[1][0], bF[1][1], bF[1][2], bF[1][3], bdl);
#pragma unroll
                for (int term = 0; term < 3; term++) {
                    const int sa = (term == 2) ? 1 : 0;
                    const int sb = (term == 1) ? 1 : 0;
#pragma unroll
                    for (int nj = 0; nj < 2; nj++)
                        MMA16816(acc[nj][0], acc[nj][1], acc[nj][2], acc[nj][3],
                                 aF[sa][0], aF[sa][1], aF[sa][2], aF[sa][3],
                                 bF[sb][nj], bF[sb][2 + nj]);
                }
            }
            // write gh to smem: rows = streams, cols = gate*32+jj layout
            int gr = lane >> 2, c2 = (lane & 3) * 2;
#pragma unroll
            for (int nj = 0; nj < 2; nj++) {
                int col = wid * 16 + nj * 8 + c2;
                *(float2*)&ghs[gr * 104 + col] = make_float2(acc[nj][0], acc[nj][1]);
                *(float2*)&ghs[(gr + 8) * 104 + col] = make_float2(acc[nj][2], acc[nj][3]);
            }
        } else {
            // gi prefetch: 384 float4 chunks (16 streams x 3 gates x 8 chunks)
            int l2 = (wid - 6) * 32 + lane;
#pragma unroll
            for (int u = 0; u < 6; u++) {
                int f = l2 + u * 64;
                int seg = f >> 3, q = f & 7;
                int s = seg / 3, g = seg % 3;
                float4 v = *(const float4*)(gi + (size_t)(m0 + s) * TT * G3 +
                                            (size_t)tq * G3 + g * 256 + j0 + q * 4);
                *(float4*)&gis[s * 104 + g * 32 + q * 4] = v;
            }
        }
        __syncthreads();

        // GRU update: 2 streams per thread
        const __nv_bfloat16* AhiC = Ab + (cur * 2 + 0) * ABUF;
        const __nv_bfloat16* AloC = Ab + (cur * 2 + 1) * ABUF;
        const uint32_t offHiB = (uint32_t)(nxt * 2 * ABUF) * 2;
        const uint32_t offLoB = offHiB + ABUF * 2;
#pragma unroll
        for (int r = 0; r < 2; r++) {
            int s = r0 + r;
            float ir  = gis[s * 104 + jj];
            float iz  = gis[s * 104 + 32 + jj];
            float inn = gis[s * 104 + 64 + jj];
            float gr_ = ghs[s * 104 + jj];
            float gz_ = ghs[s * 104 + 32 + jj];
            float gn_ = ghs[s * 104 + 64 + jj];
            float rg = sigm(ir + gr_ + b0);
            float zg = sigm(iz + gz_ + b1);
            float ng = tanhf(inn + rg * (gn_ + b2));
            float hold = __bfloat162float(AhiC[s * ABST + j]) +
                         __bfloat162float(AloC[s * ABST + j]);
            float hnew = (1.f - zg) * ng + zg * hold;
            int sidx = m0 + s - dd * S;
            seqout[((size_t)sidx * TT + tq) * D2 + dd * HIDN + j] = hnew;
            __nv_bfloat16 hh = __float2bfloat16(hnew);
            __nv_bfloat16 hl = __float2bfloat16(hnew - __bfloat162float(hh));
            uint16_t vh = __bfloat16_as_ushort(hh), vl = __bfloat16_as_ushort(hl);
            uint32_t eo = (uint32_t)(s * ABST + j) * 2;
#pragma unroll
            for (int rk = 0; rk < 8; rk++) {
                asm volatile("st.shared::cluster.u16 [%0], %1;"
                             :: "r"(peer[rk] + offHiB + eo), "h"(vh) : "memory");
                asm volatile("st.shared::cluster.u16 [%0], %1;"
                             :: "r"(peer[rk] + offLoB + eo), "h"(vl) : "memory");
            }
        }
        cluster_sync_();
    }
}

// ---------------- BiDAF prep / softmax / q2c / rank ----------------
__global__ void __launch_bounds__(256) bidaf_prep(
    const float* __restrict__ cbase, const float* __restrict__ qbase,
    const float* __restrict__ w)
{
    __shared__ float red[256];
    int i = blockIdx.x, z = blockIdx.y, tid = threadIdx.x;
    const float* c = cbase + ((size_t)z * TT + i) * D2;
    const float* q = qbase + ((size_t)z * TT + i) * D2;
    float c0 = c[tid], c1 = c[tid + 256];
    float q0 = q[tid], q1 = q[tid + 256];
    float sc = c0 * w[tid] + c1 * w[tid + 256];
    float sq = q0 * w[512 + tid] + q1 * w[768 + tid];
    float* csc = g_csc + ((size_t)z * TT + i) * D2;
    csc[tid]       = c0 * w[1024 + tid];
    csc[tid + 256] = c1 * w[1280 + tid];
    float rc = blk_sum(sc, red);
    float rq = blk_sum(sq, red);
    if (tid == 0) { g_cw[z * TT + i] = rc; g_qw[z * TT + i] = rq; }
}

__global__ void __launch_bounds__(256) softmax_row()
{
    __shared__ float red[256];
    int i = blockIdx.x, z = blockIdx.y, tid = threadIdx.x;
    float* row = g_Sc + ((size_t)z * TT + i) * TT;
    float v = row[tid];
    float mx = blk_max(v, red);
    float e = __expf(v - mx);
    float sm = blk_sum(e, red);
    row[tid] = e / sm;
    if (tid == 0) g_mrow[z * TT + i] = mx;
}

__global__ void __launch_bounds__(256) q2c_kern(const float* __restrict__ cbase)
{
    __shared__ float red[256];
    __shared__ float bbuf[256];
    int z = blockIdx.x, tid = threadIdx.x;
    float v = g_mrow[z * TT + tid];
    float mx = blk_max(v, red);
    float e = __expf(v - mx);
    float sm = blk_sum(e, red);
    bbuf[tid] = e / sm;
    __syncthreads();
    const float* c = cbase + (size_t)z * TT * D2;
    float a0 = 0.f, a1 = 0.f;
    for (int i = 0; i < TT; i++) {
        float b = bbuf[i];
        a0 += b * c[(size_t)i * D2 + tid];
        a1 += b * c[(size_t)i * D2 + tid + 256];
    }
    g_q2c[(size_t)z * D2 + tid] = a0;
    g_q2c[(size_t)z * D2 + tid + 256] = a1;
}

__global__ void __launch_bounds__(256) rank_partial(const float* __restrict__ rw)
{
    __shared__ float red[256];
    int chunk = blockIdx.x, bo = blockIdx.y, tid = threadIdx.x;
    const float* s0 = g_att + (size_t)(bo * 2) * TT * D8;
    const float* s1 = g_att + (size_t)(bo * 2 + 1) * TT * D8;
    float acc = 0.f;
    int e0 = chunk * 8192 + tid;
#pragma unroll 4
    for (int it = 0; it < 32; it++) {
        int e = e0 + it * 256;
        acc += fmaxf(s0[e], s1[e]) * rw[e];
    }
    float r = blk_sum(acc, red);
    if (tid == 0) g_part[bo * 64 + chunk] = r;
}

__global__ void rank_final(const float* __restrict__ rb, float* __restrict__ out)
{
    __shared__ float red[64];
    int bo = blockIdx.x, tid = threadIdx.x;
    red[tid] = g_part[bo * 64 + tid];
    __syncthreads();
    for (int o = 32; o > 0; o >>= 1) {
        if (tid < o) red[tid] += red[tid + o];
        __syncthreads();
    }
    if (tid == 0) out[bo] = red[0] + rb[0];
}

// ---------------- host ----------------
extern "C" void kernel_launch(void* const* d_in, const int* in_sizes, int n_in,
                              void* d_out, int out_size)
{
    const int*   question = (const int*)d_in[0];
    const int*   article  = (const int*)d_in[1];
    const float* emb      = (const float*)d_in[2];
    const float* g1_wih   = (const float*)d_in[3];
    const float* g1_whh   = (const float*)d_in[4];
    const float* g1_bih   = (const float*)d_in[5];
    const float* g1_bhh   = (const float*)d_in[6];
    const float* g2_wih   = (const float*)d_in[7];
    const float* g2_whh   = (const float*)d_in[8];
    const float* g2_bih   = (const float*)d_in[9];
    const float* g2_bhh   = (const float*)d_in[10];
    const float* b1_w     = (const float*)d_in[11];
    const float* b1_b     = (const float*)d_in[12];
    const float* b2_w     = (const float*)d_in[13];
    const float* b2_b     = (const float*)d_in[14];
    const float* rank_w   = (const float*)d_in[15];
    const float* rank_b   = (const float*)d_in[16];
    float* out = (float*)d_out;

    float *xcat, *gi1, *gi2, *hcat, *h2out, *att, *csc, *Sc, *cwp, *qwp;
    cudaGetSymbolAddress((void**)&xcat, g_xcat);
    cudaGetSymbolAddress((void**)&gi1,  g_gi1);
    cudaGetSymbolAddress((void**)&gi2,  g_gi2);
    cudaGetSymbolAddress((void**)&hcat, g_hcat);
    cudaGetSymbolAddress((void**)&h2out,g_h2out);
    cudaGetSymbolAddress((void**)&att,  g_att);
    cudaGetSymbolAddress((void**)&csc,  g_csc);
    cudaGetSymbolAddress((void**)&Sc,   g_Sc);
    cudaGetSymbolAddress((void**)&cwp,  g_cw);
    cudaGetSymbolAddress((void**)&qwp,  g_qw);

    cudaFuncSetAttribute(gru_scan_mma, cudaFuncAttributeMaxDynamicSharedMemorySize, SCAN2_SMEM);

    // 1. embed
    gather_embed<<<dim3(TT, S1), 256>>>(question, article, emb);

    // 2. gi1 = xcat @ wih1^T + bih1
    gemm_mma<<<dim3(G3/64, (S1*TT)/128, 2), 256>>>(
        xcat, g1_wih, gi1, g1_bih, S1*TT, HIDN);

    // 3. layer-1 scan (tensor-core persistent)
    gru_scan_mma<<<dim3(8, M1/16), 256, SCAN2_SMEM>>>(gi1, g1_whh, g1_bhh, hcat, S1);

    // 4. BiDAF1
    const float* cb1 = hcat;
    const float* qb1 = hcat + (size_t)64 * TT * D2;
    bidaf_prep<<<dim3(TT, S2), 256>>>(cb1, qb1, b1_w);
    gemm_awt<<<dim3(TT/64, TT/128, S2), 256>>>(
        csc, qb1, Sc, TT, TT, D2,
        (long long)TT*D2, (long long)TT*D2, (long long)TT*TT,
        cwp, qwp, b1_b);
    softmax_row<<<dim3(TT, S2), 256>>>();
    q2c_kern<<<S2, 256>>>(cb1);
    gemm_c2q<<<dim3(D2/64, TT/128, S2), 256>>>(
        Sc, qb1, (long long)TT*D2, cb1, (long long)TT*D2, att, 0);

    // 5. gi2 = att @ wih2^T + bih2
    gemm_mma<<<dim3(G3/64, (S2*TT)/128, 2), 256>>>(
        att, g2_wih, gi2, g2_bih, S2*TT, D8);

    // 6. layer-2 scan
    gru_scan_mma<<<dim3(8, M2/16), 256, SCAN2_SMEM>>>(gi2, g2_whh, g2_bhh, h2out, S2);

    // 7. BiDAF2 (accumulate into att)
    bidaf_prep<<<dim3(TT, S2), 256>>>(h2out, h2out, b2_w);
    gemm_awt<<<dim3(TT/64, TT/128, S2), 256>>>(
        csc, h2out, Sc, TT, TT, D2,
        (long long)TT*D2, (long long)TT*D2, (long long)TT*TT,
        cwp, qwp, b2_b);
    softmax_row<<<dim3(TT, S2), 256>>>();
    q2c_kern<<<S2, 256>>>(h2out);
    gemm_c2q<<<dim3(D2/64, TT/128, S2), 256>>>(
        Sc, h2out, (long long)TT*D2, h2out, (long long)TT*D2, att, 1);

    // 8. rank
    rank_partial<<<dim3(64, 32), 256>>>(rank_w);
    rank_final<<<32, 64>>>(rank_b, out);
}